// round 15
// baseline (speedup 1.0000x reference)
#include <cuda_runtime.h>
#include <cuda_bf16.h>
#include <cstdint>
#include <math.h>

#define N_NODES 100000
#define N_EDGES 260000
#define BGRAPH  4096
#define H       300
#define H2      600
#define LAYERS  5
#define FE      16
#define BN_EPS  1e-5f
#define SCB     ((N_NODES + 1023) / 1024)

// padded plane geometry (ushort elements)
#define AROWS   100096
#define ASTR    304
#define VTSTR   304
#define Z1STR   608
#define WNP_SEG  (320 * 304)
#define VW1P_SEG (640 * 304)
#define VW2P_SEG (320 * 608)
#define WNP_BASE  0
#define VW1P_BASE (LAYERS * WNP_SEG)
#define VW2P_BASE (VW1P_BASE + (LAYERS - 1) * VW1P_SEG)
#define WTOTP     (VW2P_BASE + (LAYERS - 1) * VW2P_SEG)
#define PADA      (AROWS * 4)

// ---------------- device scratch -----------------------------------------------
__device__ float g_x[N_NODES * H];
__device__ float g_hp[N_NODES * H];
__device__ float g_acc[N_NODES * H];
__device__ float g_deg[N_NODES];
__device__ int   g_indeg[N_NODES];
__device__ int   g_cursor[N_NODES];
__device__ int   g_rowptr[N_NODES + 1];
__device__ int   g_part[SCB];
__device__ int   g_csr[N_EDGES];
__device__ int   g_csrc[N_EDGES];
__device__ float g_enorm[N_EDGES];
__device__ float g_cef[N_EDGES * FE];
__device__ int   g_gcnt[BGRAPH];
__device__ int   g_grow[BGRAPH + 1];
__device__ float g_vfeat[BGRAPH * H];
__device__ float g_vtmp[BGRAPH * H];
__device__ float g_z1[BGRAPH * H2];
__device__ float g_sum[H2];
__device__ float g_sumsq[H2];
__device__ float g_vsumB[H2];
__device__ float g_vsqB[H2];
__device__ unsigned short g_ah[AROWS * ASTR];
__device__ unsigned short g_am2[AROWS * ASTR];
__device__ unsigned short g_al[AROWS * ASTR];
__device__ unsigned short g_vth[BGRAPH * VTSTR];
__device__ unsigned short g_vtm[BGRAPH * VTSTR];
__device__ unsigned short g_vtl[BGRAPH * VTSTR];
__device__ unsigned short g_z1h[BGRAPH * Z1STR];
__device__ unsigned short g_z1m[BGRAPH * Z1STR];
__device__ unsigned short g_z1l[BGRAPH * Z1STR];
__device__ unsigned short g_wh[WTOTP];
__device__ unsigned short g_wm[WTOTP];
__device__ unsigned short g_wl[WTOTP];

static inline int cdiv(int a, int b) { return (a + b - 1) / b; }

__device__ __forceinline__ void split3(float v, unsigned short& h,
                                       unsigned short& m, unsigned short& l) {
    __nv_bfloat16 hb = __float2bfloat16(v);
    float r1 = v - __bfloat162float(hb);
    __nv_bfloat16 mb = __float2bfloat16(r1);
    float r2 = r1 - __bfloat162float(mb);
    __nv_bfloat16 lb = __float2bfloat16(r2);
    h = __bfloat16_as_ushort(hb);
    m = __bfloat16_as_ushort(mb);
    l = __bfloat16_as_ushort(lb);
}

// ---------------- init ----------------------------------------------------------
__global__ void k_init0(const float* __restrict__ Wn,
                        const float* __restrict__ vW1,
                        const float* __restrict__ vW2) {
    int i = blockIdx.x * blockDim.x + threadIdx.x;
    if (i < N_NODES) { g_indeg[i] = 0; g_cursor[i] = 0; }
    if (i < BGRAPH) g_gcnt[i] = 0;
    if (i < WTOTP) {
        float v = 0.f;
        if (i < VW1P_BASE) {
            int l = i / WNP_SEG, r = i % WNP_SEG;
            int n = r / 304, k = r % 304;
            if (n < H && k < H) v = Wn[(size_t)l * H * H + k * H + n];
        } else if (i < VW2P_BASE) {
            int e = i - VW1P_BASE;
            int l = e / VW1P_SEG, r = e % VW1P_SEG;
            int n = r / 304, k = r % 304;
            if (n < H2 && k < H) v = vW1[(size_t)l * H * H2 + k * H2 + n];
        } else {
            int e = i - VW2P_BASE;
            int l = e / VW2P_SEG, r = e % VW2P_SEG;
            int n = r / 608, k = r % 608;
            if (n < H && k < H2) v = vW2[(size_t)l * H2 * H + k * H + n];
        }
        unsigned short h, m, lo;
        split3(v, h, m, lo);
        g_wh[i] = h; g_wm[i] = m; g_wl[i] = lo;
    }
    if (i < PADA) {
        size_t o = (size_t)(i >> 2) * ASTR + 300 + (i & 3);
        g_ah[o] = 0; g_am2[o] = 0; g_al[o] = 0;
    }
    if (i < 96 * ASTR) {
        size_t o = (size_t)(N_NODES + i / ASTR) * ASTR + (i % ASTR);
        g_ah[o] = 0; g_am2[o] = 0; g_al[o] = 0;
    }
    if (i < BGRAPH * 4) {
        size_t o = (size_t)(i >> 2) * VTSTR + 300 + (i & 3);
        g_vth[o] = 0; g_vtm[o] = 0; g_vtl[o] = 0;
    }
    if (i < BGRAPH * 8) {
        size_t o = (size_t)(i >> 3) * Z1STR + 600 + (i & 7);
        g_z1h[o] = 0; g_z1m[o] = 0; g_z1l[o] = 0;
    }
}

__global__ void k_count(const int* __restrict__ dst, const int* __restrict__ gid) {
    int i = blockIdx.x * blockDim.x + threadIdx.x;
    if (i < N_EDGES) atomicAdd(&g_indeg[dst[i]], 1);
    if (i < N_NODES) atomicAdd(&g_gcnt[gid[i]], 1);
}

__global__ void k_init3(const float* __restrict__ node_emb,
                        const int* __restrict__ node_types,
                        const float* __restrict__ vn_emb) {
    int idx = blockIdx.x * blockDim.x + threadIdx.x;
    if (idx < N_NODES * H) {
        int n = idx / H, j = idx - n * H;
        float hv = node_emb[node_types[n] * H + j];
        g_x[idx] = hv;
        unsigned short h, m, lo;
        split3(hv + vn_emb[j], h, m, lo);
        size_t o = (size_t)n * ASTR + j;
        g_ah[o] = h; g_am2[o] = m; g_al[o] = lo;
    }
    if (idx < BGRAPH * H) g_vfeat[idx] = vn_emb[idx % H];
    if (idx < N_NODES) g_deg[idx] = (float)g_indeg[idx] + 1.0f;
}

// ---------------- CSR build ----------------------------------------------------

__global__ void k_scanA() {
    __shared__ int sh[1024];
    int t = threadIdx.x;
    int idx = blockIdx.x * 1024 + t;
    sh[t] = (idx < N_NODES) ? g_indeg[idx] : 0;
    __syncthreads();
    for (int s = 512; s > 0; s >>= 1) {
        if (t < s) sh[t] += sh[t + s];
        __syncthreads();
    }
    if (t == 0) g_part[blockIdx.x] = sh[0];
}

__global__ void k_scanB() {
    int run = 0;
    for (int b = 0; b < SCB; b++) { int v = g_part[b]; g_part[b] = run; run += v; }
    g_rowptr[N_NODES] = run;
}

__global__ void k_scanC() {
    __shared__ int sh[1024];
    int t = threadIdx.x;
    int idx = blockIdx.x * 1024 + t;
    int v = (idx < N_NODES) ? g_indeg[idx] : 0;
    sh[t] = v;
    __syncthreads();
    for (int off = 1; off < 1024; off <<= 1) {
        int x = (t >= off) ? sh[t - off] : 0;
        __syncthreads();
        sh[t] += x;
        __syncthreads();
    }
    if (idx < N_NODES) g_rowptr[idx] = g_part[blockIdx.x] + sh[t] - v;
}

__global__ void k_csrfill(const int* __restrict__ dst) {
    int e = blockIdx.x * blockDim.x + threadIdx.x;
    if (e < N_EDGES) {
        int d = dst[e];
        int pos = g_rowptr[d] + atomicAdd(&g_cursor[d], 1);
        g_csr[pos] = e;
    }
}

__global__ void k_csrdata(const int* __restrict__ src, const int* __restrict__ dst,
                          const float* __restrict__ ef) {
    int idx = blockIdx.x * blockDim.x + threadIdx.x;
    if (idx < N_EDGES) {
        int eid = g_csr[idx];
        int s = src[eid];
        g_csrc[idx] = s;
        g_enorm[idx] = rsqrtf(g_deg[s] * g_deg[dst[eid]]);
    }
    if (idx < N_EDGES * FE) {
        int pos = idx >> 4, k = idx & 15;
        g_cef[idx] = ef[(size_t)g_csr[pos] * FE + k];
    }
}

__global__ void k_gscan() {
    __shared__ int sh[1024];
    int t = threadIdx.x;
    int b4 = t * 4;
    int a0 = g_gcnt[b4], a1 = g_gcnt[b4 + 1], a2 = g_gcnt[b4 + 2], a3 = g_gcnt[b4 + 3];
    int s = a0 + a1 + a2 + a3;
    sh[t] = s;
    __syncthreads();
    for (int off = 1; off < 1024; off <<= 1) {
        int v = (t >= off) ? sh[t - off] : 0;
        __syncthreads();
        sh[t] += v;
        __syncthreads();
    }
    int excl = sh[t] - s;
    g_grow[b4] = excl;
    g_grow[b4 + 1] = excl + a0;
    g_grow[b4 + 2] = excl + a0 + a1;
    g_grow[b4 + 3] = excl + a0 + a1 + a2;
    if (t == 1023) g_grow[BGRAPH] = sh[1023];
}

// ---------------- virtual-node segment sum -> vtmp split planes ----------------
__global__ void k_vsum() {
    int b = blockIdx.x;
    int j = threadIdx.x;
    if (j >= H) return;
    int r0 = g_grow[b], r1 = g_grow[b + 1];
    float s = 0.f;
    for (int n = r0; n < r1; n++) s += g_x[(size_t)n * H + j];
    float v = s + (float)(r1 - r0 + 1) * g_vfeat[(size_t)b * H + j];
    unsigned short h, m, lo;
    split3(v, h, m, lo);
    size_t o = (size_t)b * VTSTR + j;
    g_vth[o] = h; g_vtm[o] = m; g_vtl[o] = lo;
}

// ---------------- split3-bf16 GEMM: 128x160, 2-stage cp.async (R13 order) ------
__device__ __forceinline__ void mma_bf16(float* c, uint32_t a0, uint32_t a1,
                                         uint32_t a2, uint32_t a3,
                                         uint32_t b0, uint32_t b1) {
    asm volatile(
        "mma.sync.aligned.m16n8k16.row.col.f32.bf16.bf16.f32 "
        "{%0,%1,%2,%3}, {%4,%5,%6,%7}, {%8,%9}, {%0,%1,%2,%3};"
        : "+f"(c[0]), "+f"(c[1]), "+f"(c[2]), "+f"(c[3])
        : "r"(a0), "r"(a1), "r"(a2), "r"(a3), "r"(b0), "r"(b1));
}

#define CP16(dst, src) \
    asm volatile("cp.async.ca.shared.global [%0], [%1], 16;" :: "r"(dst), "l"(src))
#define CP_COMMIT() asm volatile("cp.async.commit_group;")
#define CP_WAIT1()  asm volatile("cp.async.wait_group 1;")
#define CP_WAIT0()  asm volatile("cp.async.wait_group 0;")

#define STG_U32 10368
#define GEMM_SMEM (2 * STG_U32 * 4)   // 82944 bytes

__global__ __launch_bounds__(256)
void k_gemm_t(const uint32_t* __restrict__ Ah, const uint32_t* __restrict__ Am,
              const uint32_t* __restrict__ Al, int aStr,
              const uint32_t* __restrict__ Bh, const uint32_t* __restrict__ Bm,
              const uint32_t* __restrict__ Bl, int bStr,
              const float* __restrict__ bias, float* __restrict__ C,
              int M, int Ncol, int nkt) {
    extern __shared__ uint32_t sm[];
    uint32_t sbase = (uint32_t)__cvta_generic_to_shared(sm);

    int tid = threadIdx.x;
    int warp = tid >> 5, lane = tid & 31;
    int wm = warp >> 2, wn = warp & 3;
    int m0 = blockIdx.y * 128, n0 = blockIdx.x * 160;
    int lg = lane >> 2, lt = lane & 3;

    float acc[4][5][4];
#pragma unroll
    for (int i = 0; i < 4; i++)
#pragma unroll
        for (int j = 0; j < 5; j++)
#pragma unroll
            for (int c = 0; c < 4; c++) acc[i][j][c] = 0.f;

    auto issue = [&](int kt, int stg) {
        uint32_t sb = sbase + stg * (STG_U32 * 4);
        int p0 = kt * 8;
#pragma unroll
        for (int i = 0; i < 3; i++) {
            int c = tid + 256 * i;
            int pl = c >> 8, rr = (c >> 1) & 127, hf = c & 1;
            const uint32_t* ap = (pl == 0) ? Ah : (pl == 1) ? Am : Al;
            const uint32_t* s = ap + (size_t)(m0 + rr) * aStr + p0 + hf * 4;
            uint32_t d = sb + (pl * 1536 + rr * 12 + hf * 4) * 4;
            CP16(d, s);
        }
#pragma unroll
        for (int i = 0; i < 4; i++) {
            int c = tid + 256 * i;
            if (c < 960) {
                int pl = c / 320, rem = c % 320, nn = rem >> 1, hf = rem & 1;
                const uint32_t* bp = (pl == 0) ? Bh : (pl == 1) ? Bm : Bl;
                const uint32_t* s = bp + (size_t)(n0 + nn) * bStr + p0 + hf * 4;
                uint32_t d = sb + (4608 + pl * 1920 + nn * 12 + hf * 4) * 4;
                CP16(d, s);
            }
        }
        CP_COMMIT();
    };

    issue(0, 0);

    for (int kt = 0; kt < nkt; kt++) {
        if (kt + 1 < nkt) {
            issue(kt + 1, (kt + 1) & 1);
            CP_WAIT1();
        } else {
            CP_WAIT0();
        }
        __syncthreads();

        const uint32_t* st = sm + (kt & 1) * STG_U32;
        const uint32_t* sAh = st;
        const uint32_t* sAm = st + 1536;
        const uint32_t* sAl = st + 3072;
        const uint32_t* sBh = st + 4608;
        const uint32_t* sBm = st + 6528;
        const uint32_t* sBl = st + 8448;

        uint32_t bh[5][2], bm[5][2], bl[5][2];
#pragma unroll
        for (int nt = 0; nt < 5; nt++) {
            int bn2 = (wn * 40 + nt * 8 + lg) * 12;
            bh[nt][0] = sBh[bn2 + lt]; bh[nt][1] = sBh[bn2 + 4 + lt];
            bm[nt][0] = sBm[bn2 + lt]; bm[nt][1] = sBm[bn2 + 4 + lt];
            bl[nt][0] = sBl[bn2 + lt]; bl[nt][1] = sBl[bn2 + 4 + lt];
        }
#pragma unroll
        for (int mt = 0; mt < 4; mt++) {
            int am = (wm * 64 + mt * 16 + lg) * 12;
            int am8 = am + 8 * 12;
            uint32_t ah0 = sAh[am + lt],      ah1 = sAh[am8 + lt];
            uint32_t ah2 = sAh[am + 4 + lt],  ah3 = sAh[am8 + 4 + lt];
            uint32_t amd0 = sAm[am + lt],     amd1 = sAm[am8 + lt];
            uint32_t amd2 = sAm[am + 4 + lt], amd3 = sAm[am8 + 4 + lt];
            uint32_t alo0 = sAl[am + lt],     alo1 = sAl[am8 + lt];
            uint32_t alo2 = sAl[am + 4 + lt], alo3 = sAl[am8 + 4 + lt];
#pragma unroll
            for (int nt = 0; nt < 5; nt++) {
                mma_bf16(acc[mt][nt], ah0, ah1, ah2, ah3, bh[nt][0], bh[nt][1]);
                mma_bf16(acc[mt][nt], ah0, ah1, ah2, ah3, bm[nt][0], bm[nt][1]);
                mma_bf16(acc[mt][nt], amd0, amd1, amd2, amd3, bh[nt][0], bh[nt][1]);
                mma_bf16(acc[mt][nt], ah0, ah1, ah2, ah3, bl[nt][0], bl[nt][1]);
                mma_bf16(acc[mt][nt], alo0, alo1, alo2, alo3, bh[nt][0], bh[nt][1]);
                mma_bf16(acc[mt][nt], amd0, amd1, amd2, amd3, bm[nt][0], bm[nt][1]);
            }
        }
        __syncthreads();
    }

    // writeout
#pragma unroll
    for (int mt = 0; mt < 4; mt++) {
#pragma unroll
        for (int nt = 0; nt < 5; nt++) {
            int gn = n0 + wn * 40 + nt * 8 + 2 * lt;
            if (gn >= Ncol) continue;
            float b0 = bias[gn], b1 = bias[gn + 1];
            int gm0 = m0 + wm * 64 + mt * 16 + lg;
            if (gm0 < M) {
                float2 o = make_float2(acc[mt][nt][0] + b0, acc[mt][nt][1] + b1);
                *(float2*)(C + (size_t)gm0 * Ncol + gn) = o;
            }
            int gm1 = gm0 + 8;
            if (gm1 < M) {
                float2 o = make_float2(acc[mt][nt][2] + b0, acc[mt][nt][3] + b1);
                *(float2*)(C + (size_t)gm1 * Ncol + gn) = o;
            }
        }
    }
}

// ---------------- node aggregation: column-slice + 1-deep edge prefetch --------
__global__ __launch_bounds__(320)
void k_agg(const float* __restrict__ be_l, const float* __restrict__ We_l,
           const float* __restrict__ res_l) {
    int tid = threadIdx.x;
    int lane = tid & 31;
    int j = tid;
    bool act = (j < H);

    float wj[16];
#pragma unroll
    for (int k = 0; k < 16; k++) wj[k] = act ? We_l[k * H + j] : 0.f;
    float bj = act ? be_l[j] : 0.f;
    float rj = act ? res_l[j] : 0.f;

    float ls = 0.f, lq = 0.f;

    for (int n = blockIdx.x; n < N_NODES; n += gridDim.x) {
        float dn = g_deg[n];
        float a = act ? fmaxf(g_hp[(size_t)n * H + j] + rj, 0.f) / dn : 0.f;
        int e0 = g_rowptr[n], e1 = g_rowptr[n + 1];
        if (e0 < e1) {
            // preload edge e0
            float nrmc = g_enorm[e0];
            float evc = (lane < FE) ? g_cef[(size_t)e0 * FE + lane] : 0.f;
            float hvc = act ? g_hp[(size_t)g_csrc[e0] * H + j] : 0.f;
            for (int e = e0; e < e1; e++) {
                // prefetch e+1 (independent of current compute)
                float nrmn = 0.f, evn = 0.f, hvn = 0.f;
                if (e + 1 < e1) {
                    nrmn = g_enorm[e + 1];
                    evn = (lane < FE) ? g_cef[(size_t)(e + 1) * FE + lane] : 0.f;
                    hvn = act ? g_hp[(size_t)g_csrc[e + 1] * H + j] : 0.f;
                }
                float ep = bj;
#pragma unroll
                for (int k = 0; k < 16; k++)
                    ep = fmaf(__shfl_sync(0xffffffffu, evc, k), wj[k], ep);
                if (act) a += nrmc * fmaxf(hvc + ep, 0.f);
                nrmc = nrmn; evc = evn; hvc = hvn;
            }
        }
        if (act) {
            g_acc[(size_t)n * H + j] = a;
            ls += a;
            lq += a * a;
        }
    }
    if (act) {
        atomicAdd(&g_sum[j], ls);
        atomicAdd(&g_sumsq[j], lq);
    }
}

// ---------------- batch norm ---------------------------------------------------

__global__ void k_zero_stats(float* __restrict__ sum, float* __restrict__ sumsq,
                             int cols) {
    int c = blockIdx.x * blockDim.x + threadIdx.x;
    if (c < cols) { sum[c] = 0.0f; sumsq[c] = 0.0f; }
}

__global__ void k_bnstat(const float* __restrict__ X, int rows, int cols,
                         float* __restrict__ sum, float* __restrict__ sumsq) {
    int r0 = blockIdx.x * 256;
    int rend = min(r0 + 256, rows);
    int t = threadIdx.x;
    float s[3] = {0, 0, 0}, q[3] = {0, 0, 0};
    for (int r = r0; r < rend; r++) {
        const float* row = X + (size_t)r * cols;
        int ci = 0;
        for (int c = t; c < cols; c += 256, ci++) {
            float v = row[c];
            s[ci] += v; q[ci] += v * v;
        }
    }
    int ci = 0;
    for (int c = t; c < cols; c += 256, ci++) {
        atomicAdd(&sum[c], s[ci]);
        atomicAdd(&sumsq[c], q[ci]);
    }
}

// BN apply with inline mean/rstd (reads sum/sumsq directly)
__global__ void k_bnap(const float* __restrict__ X, float* __restrict__ Y,
                       const float* __restrict__ gamma,
                       const float* __restrict__ beta,
                       const float* __restrict__ sum,
                       const float* __restrict__ sumsq,
                       float inv_rows,
                       int rows, int cols, int do_relu,
                       unsigned short* __restrict__ ph,
                       unsigned short* __restrict__ pm,
                       unsigned short* __restrict__ pl,
                       int pstride,
                       const int* __restrict__ gid,
                       const float* __restrict__ vfeat) {
    int idx = blockIdx.x * blockDim.x + threadIdx.x;
    if (idx < rows * cols) {
        int r = idx / cols, c = idx - r * cols;
        float mn = sum[c] * inv_rows;
        float rs = rsqrtf(sumsq[c] * inv_rows - mn * mn + BN_EPS);
        float v = (X[idx] - mn) * rs * gamma[c] + beta[c];
        if (do_relu) v = fmaxf(v, 0.0f);
        if (Y) Y[idx] = v;
        if (ph) {
            float p = v;
            if (gid) p += vfeat[(size_t)gid[r] * cols + c];
            unsigned short h, m, lo;
            split3(p, h, m, lo);
            size_t o = (size_t)r * pstride + c;
            ph[o] = h; pm[o] = m; pl[o] = lo;
        }
    }
}

// ---------------- host orchestration -------------------------------------------

extern "C" void kernel_launch(void* const* d_in, const int* in_sizes, int n_in,
                              void* d_out, int out_size) {
    const int *node_types, *src, *dst, *gid;
    const float *edge_feats, *node_emb, *Wn, *bn_lin, *We, *be, *res_emb,
                *bn_gamma, *bn_beta, *vn_emb, *vW1, *vb1, *vg1, *vbt1,
                *vW2, *vb2, *vg2, *vbt2;

    if (in_sizes[0] == N_NODES) {
        node_types = (const int*)d_in[0];
        edge_feats = (const float*)d_in[1];
        src        = (const int*)d_in[2];
        dst        = (const int*)d_in[3];
        gid        = (const int*)d_in[4];
        node_emb = (const float*)d_in[6];
        Wn       = (const float*)d_in[7];
        bn_lin   = (const float*)d_in[8];
        We       = (const float*)d_in[9];
        be       = (const float*)d_in[10];
        res_emb  = (const float*)d_in[11];
        bn_gamma = (const float*)d_in[12];
        bn_beta  = (const float*)d_in[13];
        vn_emb   = (const float*)d_in[14];
        vW1  = (const float*)d_in[15];
        vb1  = (const float*)d_in[16];
        vg1  = (const float*)d_in[17];
        vbt1 = (const float*)d_in[18];
        vW2  = (const float*)d_in[19];
        vb2  = (const float*)d_in[20];
        vg2  = (const float*)d_in[21];
        vbt2 = (const float*)d_in[22];
    } else {
        edge_feats = (const float*)d_in[0];
        node_emb = (const float*)d_in[1];
        Wn       = (const float*)d_in[2];
        bn_lin   = (const float*)d_in[3];
        We       = (const float*)d_in[4];
        be       = (const float*)d_in[5];
        res_emb  = (const float*)d_in[6];
        bn_gamma = (const float*)d_in[7];
        bn_beta  = (const float*)d_in[8];
        vn_emb   = (const float*)d_in[9];
        vW1  = (const float*)d_in[10];
        vb1  = (const float*)d_in[11];
        vg1  = (const float*)d_in[12];
        vbt1 = (const float*)d_in[13];
        vW2  = (const float*)d_in[14];
        vb2  = (const float*)d_in[15];
        vg2  = (const float*)d_in[16];
        vbt2 = (const float*)d_in[17];
        node_types = (const int*)d_in[18];
        src        = (const int*)d_in[19];
        dst        = (const int*)d_in[20];
        gid        = (const int*)d_in[21];
    }

    const int NH = N_NODES * H;
    const int BH = BGRAPH * H;
    const int TPB = 256;

    float *g_x_p, *g_hp_p, *g_acc_p, *g_vtmp_p, *g_vfeat_p, *g_z1_p;
    cudaGetSymbolAddress((void**)&g_x_p, g_x);
    cudaGetSymbolAddress((void**)&g_hp_p, g_hp);
    cudaGetSymbolAddress((void**)&g_acc_p, g_acc);
    cudaGetSymbolAddress((void**)&g_vtmp_p, g_vtmp);
    cudaGetSymbolAddress((void**)&g_vfeat_p, g_vfeat);
    cudaGetSymbolAddress((void**)&g_z1_p, g_z1);
    float *sum_p, *sq_p, *vsum_p, *vsq_p;
    cudaGetSymbolAddress((void**)&sum_p, g_sum);
    cudaGetSymbolAddress((void**)&sq_p, g_sumsq);
    cudaGetSymbolAddress((void**)&vsum_p, g_vsumB);
    cudaGetSymbolAddress((void**)&vsq_p, g_vsqB);
    unsigned short *ah_p, *am_p, *al_p, *vth_p, *vtm_p, *vtl_p,
                   *z1h_p, *z1m_p, *z1l_p, *wh_p, *wm_p, *wl_p;
    cudaGetSymbolAddress((void**)&ah_p, g_ah);
    cudaGetSymbolAddress((void**)&am_p, g_am2);
    cudaGetSymbolAddress((void**)&al_p, g_al);
    cudaGetSymbolAddress((void**)&vth_p, g_vth);
    cudaGetSymbolAddress((void**)&vtm_p, g_vtm);
    cudaGetSymbolAddress((void**)&vtl_p, g_vtl);
    cudaGetSymbolAddress((void**)&z1h_p, g_z1h);
    cudaGetSymbolAddress((void**)&z1m_p, g_z1m);
    cudaGetSymbolAddress((void**)&z1l_p, g_z1l);
    cudaGetSymbolAddress((void**)&wh_p, g_wh);
    cudaGetSymbolAddress((void**)&wm_p, g_wm);
    cudaGetSymbolAddress((void**)&wl_p, g_wl);
    const uint32_t* Ah = (const uint32_t*)ah_p;
    const uint32_t* Am = (const uint32_t*)am_p;
    const uint32_t* Al = (const uint32_t*)al_p;
    const uint32_t* VTh = (const uint32_t*)vth_p;
    const uint32_t* VTm = (const uint32_t*)vtm_p;
    const uint32_t* VTl = (const uint32_t*)vtl_p;
    const uint32_t* Z1h = (const uint32_t*)z1h_p;
    const uint32_t* Z1m = (const uint32_t*)z1m_p;
    const uint32_t* Z1l = (const uint32_t*)z1l_p;

    cudaFuncSetAttribute(k_gemm_t, cudaFuncAttributeMaxDynamicSharedMemorySize,
                         GEMM_SMEM);

    static cudaStream_t s2 = nullptr;
    static cudaEvent_t ev_fork = nullptr, ev_join = nullptr;
    if (!s2) {
        cudaStreamCreateWithFlags(&s2, cudaStreamNonBlocking);
        cudaEventCreateWithFlags(&ev_fork, cudaEventDisableTiming);
        cudaEventCreateWithFlags(&ev_join, cudaEventDisableTiming);
    }

    k_init0<<<cdiv(WTOTP, TPB), TPB>>>(Wn, vW1, vW2);
    k_count<<<cdiv(N_EDGES, TPB), TPB>>>(dst, gid);
    k_init3<<<cdiv(NH, TPB), TPB>>>(node_emb, node_types, vn_emb);

    dim3 node_grid(2, AROWS / 128);
    const float invN = 1.0f / (float)N_NODES;
    const float invB = 1.0f / (float)BGRAPH;

    for (int l = 0; l < LAYERS; l++) {
        const float* bnl_l = bn_lin + l * H;
        const float* We_l  = We + (size_t)l * FE * H;
        const float* be_l  = be + l * H;
        const float* res_l = res_emb + l * H;
        const float* gam_l = bn_gamma + l * H;
        const float* bet_l = bn_beta + l * H;
        const uint32_t* Wnh = (const uint32_t*)(wh_p + WNP_BASE + (size_t)l * WNP_SEG);
        const uint32_t* Wnm = (const uint32_t*)(wm_p + WNP_BASE + (size_t)l * WNP_SEG);
        const uint32_t* Wnl = (const uint32_t*)(wl_p + WNP_BASE + (size_t)l * WNP_SEG);

        bool has_vn = (l < LAYERS - 1);

        // ---- node GEMM first (4th launch at l=0 -> ncu slot) ----
        k_gemm_t<<<node_grid, 256, GEMM_SMEM>>>(Ah, Am, Al, 152,
                                                Wnh, Wnm, Wnl, 152,
                                                bnl_l, g_hp_p, N_NODES, H, 19);

        // ---- fork: vn chain on s2 (overlaps with CSR build / k_agg below) ----
        if (has_vn) {
            const float* vb1_l  = vb1 + l * H2;
            const float* vg1_l  = vg1 + l * H2;
            const float* vbt1_l = vbt1 + l * H2;
            const float* vb2_l  = vb2 + l * H;
            const float* vg2_l  = vg2 + l * H;
            const float* vbt2_l = vbt2 + l * H;
            const uint32_t* W1h = (const uint32_t*)(wh_p + VW1P_BASE + (size_t)l * VW1P_SEG);
            const uint32_t* W1m = (const uint32_t*)(wm_p + VW1P_BASE + (size_t)l * VW1P_SEG);
            const uint32_t* W1l = (const uint32_t*)(wl_p + VW1P_BASE + (size_t)l * VW1P_SEG);
            const uint32_t* W2h = (const uint32_t*)(wh_p + VW2P_BASE + (size_t)l * VW2P_SEG);
            const uint32_t* W2m = (const uint32_t*)(wm_p + VW2P_BASE + (size_t)l * VW2P_SEG);
            const uint32_t* W2l = (const uint32_t*)(wl_p + VW2P_BASE + (size_t)l * VW2P_SEG);

            cudaEventRecord(ev_fork, 0);
            cudaStreamWaitEvent(s2, ev_fork, 0);

            if (l == 0) k_gscan<<<1, 1024, 0, s2>>>();
            k_vsum<<<BGRAPH, 320, 0, s2>>>();
            dim3 g1(4, BGRAPH / 128);
            k_gemm_t<<<g1, 256, GEMM_SMEM, s2>>>(VTh, VTm, VTl, 152,
                                                 W1h, W1m, W1l, 152,
                                                 vb1_l, g_z1_p, BGRAPH, H2, 19);
            k_zero_stats<<<cdiv(H2, TPB), TPB, 0, s2>>>(vsum_p, vsq_p, H2);
            k_bnstat<<<cdiv(BGRAPH, 256), 256, 0, s2>>>(g_z1_p, BGRAPH, H2,
                                                        vsum_p, vsq_p);
            k_bnap<<<cdiv(BGRAPH * H2, TPB), TPB, 0, s2>>>(
                g_z1_p, nullptr, vg1_l, vbt1_l, vsum_p, vsq_p, invB,
                BGRAPH, H2, 1, z1h_p, z1m_p, z1l_p, Z1STR, nullptr, nullptr);

            dim3 g2(2, BGRAPH / 128);
            k_gemm_t<<<g2, 256, GEMM_SMEM, s2>>>(Z1h, Z1m, Z1l, 304,
                                                 W2h, W2m, W2l, 304,
                                                 vb2_l, g_vtmp_p, BGRAPH, H, 38);
            k_zero_stats<<<cdiv(H, TPB), TPB, 0, s2>>>(vsum_p, vsq_p, H);
            k_bnstat<<<cdiv(BGRAPH, 256), 256, 0, s2>>>(g_vtmp_p, BGRAPH, H,
                                                        vsum_p, vsq_p);
            k_bnap<<<cdiv(BH, TPB), TPB, 0, s2>>>(
                g_vtmp_p, g_vfeat_p, vg2_l, vbt2_l, vsum_p, vsq_p, invB,
                BGRAPH, H, 1, nullptr, nullptr, nullptr, 0, nullptr, nullptr);

            cudaEventRecord(ev_join, s2);
        }

        if (l == 0) {
            k_scanA<<<SCB, 1024>>>();
            k_scanB<<<1, 1>>>();
            k_scanC<<<SCB, 1024>>>();
            k_csrfill<<<cdiv(N_EDGES, TPB), TPB>>>(dst);
            k_csrdata<<<cdiv(N_EDGES * FE, TPB), TPB>>>(src, dst, edge_feats);
        }

        k_zero_stats<<<cdiv(H, TPB), TPB>>>(sum_p, sq_p, H);
        k_agg<<<888, 320>>>(be_l, We_l, res_l);

        if (has_vn) {
            cudaStreamWaitEvent(0, ev_join, 0);
            k_bnap<<<cdiv(NH, TPB), TPB>>>(g_acc_p, g_x_p, gam_l, bet_l,
                                           sum_p, sq_p, invN, N_NODES, H, 1,
                                           ah_p, am_p, al_p, ASTR,
                                           gid, g_vfeat_p);
        } else {
            k_bnap<<<cdiv(NH, TPB), TPB>>>(g_acc_p, (float*)d_out, gam_l, bet_l,
                                           sum_p, sq_p, invN, N_NODES, H, 0,
                                           nullptr, nullptr, nullptr, 0,
                                           nullptr, nullptr);
        }
    }
}

// round 16
// speedup vs baseline: 1.1023x; 1.1023x over previous
#include <cuda_runtime.h>
#include <cuda_bf16.h>
#include <cstdint>
#include <math.h>

#define N_NODES 100000
#define N_EDGES 260000
#define BGRAPH  4096
#define H       300
#define H2      600
#define LAYERS  5
#define FE      16
#define BN_EPS  1e-5f
#define SCB     ((N_NODES + 1023) / 1024)

// padded plane geometry (ushort elements)
#define AROWS   100096
#define ASTR    304
#define VTSTR   304
#define Z1STR   608
#define WNP_SEG  (320 * 304)
#define VW1P_SEG (640 * 304)
#define VW2P_SEG (320 * 608)
#define WNP_BASE  0
#define VW1P_BASE (LAYERS * WNP_SEG)
#define VW2P_BASE (VW1P_BASE + (LAYERS - 1) * VW1P_SEG)
#define WTOTP     (VW2P_BASE + (LAYERS - 1) * VW2P_SEG)
#define PADA      (AROWS * 4)

// ---------------- device scratch -----------------------------------------------
__device__ float g_x[N_NODES * H];
__device__ float g_hp[N_NODES * H];
__device__ float g_acc[N_NODES * H];
__device__ float g_deg[N_NODES];
__device__ int   g_indeg[N_NODES];
__device__ int   g_cursor[N_NODES];
__device__ int   g_rowptr[N_NODES + 1];
__device__ int   g_part[SCB];
__device__ int   g_csr[N_EDGES];
__device__ int   g_csrc[N_EDGES];
__device__ float g_enorm[N_EDGES];
__device__ float g_cef[N_EDGES * FE];
__device__ int   g_gcnt[BGRAPH];
__device__ int   g_grow[BGRAPH + 1];
__device__ float g_vfeat[BGRAPH * H];
__device__ float g_vtmp[BGRAPH * H];
__device__ float g_z1[BGRAPH * H2];
__device__ float g_sum[H2];
__device__ float g_sumsq[H2];
__device__ float g_mean[H2];
__device__ float g_rstd[H2];
__device__ float g_vsumB[H2];
__device__ float g_vsqB[H2];
__device__ float g_vmeanB[H2];
__device__ float g_vrstdB[H2];
__device__ unsigned short g_ah[AROWS * ASTR];
__device__ unsigned short g_am2[AROWS * ASTR];
__device__ unsigned short g_al[AROWS * ASTR];
__device__ unsigned short g_vth[BGRAPH * VTSTR];
__device__ unsigned short g_vtm[BGRAPH * VTSTR];
__device__ unsigned short g_vtl[BGRAPH * VTSTR];
__device__ unsigned short g_z1h[BGRAPH * Z1STR];
__device__ unsigned short g_z1m[BGRAPH * Z1STR];
__device__ unsigned short g_z1l[BGRAPH * Z1STR];
__device__ unsigned short g_wh[WTOTP];
__device__ unsigned short g_wm[WTOTP];
__device__ unsigned short g_wl[WTOTP];

static inline int cdiv(int a, int b) { return (a + b - 1) / b; }

__device__ __forceinline__ void split3(float v, unsigned short& h,
                                       unsigned short& m, unsigned short& l) {
    __nv_bfloat16 hb = __float2bfloat16(v);
    float r1 = v - __bfloat162float(hb);
    __nv_bfloat16 mb = __float2bfloat16(r1);
    float r2 = r1 - __bfloat162float(mb);
    __nv_bfloat16 lb = __float2bfloat16(r2);
    h = __bfloat16_as_ushort(hb);
    m = __bfloat16_as_ushort(mb);
    l = __bfloat16_as_ushort(lb);
}

// ---------------- init ----------------------------------------------------------
__global__ void k_init0(const float* __restrict__ Wn,
                        const float* __restrict__ vW1,
                        const float* __restrict__ vW2) {
    int i = blockIdx.x * blockDim.x + threadIdx.x;
    if (i < N_NODES) { g_indeg[i] = 0; g_cursor[i] = 0; }
    if (i < BGRAPH) g_gcnt[i] = 0;
    if (i < WTOTP) {
        float v = 0.f;
        if (i < VW1P_BASE) {
            int l = i / WNP_SEG, r = i % WNP_SEG;
            int n = r / 304, k = r % 304;
            if (n < H && k < H) v = Wn[(size_t)l * H * H + k * H + n];
        } else if (i < VW2P_BASE) {
            int e = i - VW1P_BASE;
            int l = e / VW1P_SEG, r = e % VW1P_SEG;
            int n = r / 304, k = r % 304;
            if (n < H2 && k < H) v = vW1[(size_t)l * H * H2 + k * H2 + n];
        } else {
            int e = i - VW2P_BASE;
            int l = e / VW2P_SEG, r = e % VW2P_SEG;
            int n = r / 608, k = r % 608;
            if (n < H && k < H2) v = vW2[(size_t)l * H2 * H + k * H + n];
        }
        unsigned short h, m, lo;
        split3(v, h, m, lo);
        g_wh[i] = h; g_wm[i] = m; g_wl[i] = lo;
    }
    if (i < PADA) {
        size_t o = (size_t)(i >> 2) * ASTR + 300 + (i & 3);
        g_ah[o] = 0; g_am2[o] = 0; g_al[o] = 0;
    }
    if (i < 96 * ASTR) {
        size_t o = (size_t)(N_NODES + i / ASTR) * ASTR + (i % ASTR);
        g_ah[o] = 0; g_am2[o] = 0; g_al[o] = 0;
    }
    if (i < BGRAPH * 4) {
        size_t o = (size_t)(i >> 2) * VTSTR + 300 + (i & 3);
        g_vth[o] = 0; g_vtm[o] = 0; g_vtl[o] = 0;
    }
    if (i < BGRAPH * 8) {
        size_t o = (size_t)(i >> 3) * Z1STR + 600 + (i & 7);
        g_z1h[o] = 0; g_z1m[o] = 0; g_z1l[o] = 0;
    }
}

__global__ void k_count(const int* __restrict__ dst, const int* __restrict__ gid) {
    int i = blockIdx.x * blockDim.x + threadIdx.x;
    if (i < N_EDGES) atomicAdd(&g_indeg[dst[i]], 1);
    if (i < N_NODES) atomicAdd(&g_gcnt[gid[i]], 1);
}

__global__ void k_init3(const float* __restrict__ node_emb,
                        const int* __restrict__ node_types,
                        const float* __restrict__ vn_emb) {
    int idx = blockIdx.x * blockDim.x + threadIdx.x;
    if (idx < N_NODES * H) {
        int n = idx / H, j = idx - n * H;
        float hv = node_emb[node_types[n] * H + j];
        g_x[idx] = hv;
        unsigned short h, m, lo;
        split3(hv + vn_emb[j], h, m, lo);
        size_t o = (size_t)n * ASTR + j;
        g_ah[o] = h; g_am2[o] = m; g_al[o] = lo;
    }
    if (idx < BGRAPH * H) g_vfeat[idx] = vn_emb[idx % H];
    if (idx < N_NODES) g_deg[idx] = (float)g_indeg[idx] + 1.0f;
}

// ---------------- CSR build ----------------------------------------------------

__global__ void k_scanA() {
    __shared__ int sh[1024];
    int t = threadIdx.x;
    int idx = blockIdx.x * 1024 + t;
    sh[t] = (idx < N_NODES) ? g_indeg[idx] : 0;
    __syncthreads();
    for (int s = 512; s > 0; s >>= 1) {
        if (t < s) sh[t] += sh[t + s];
        __syncthreads();
    }
    if (t == 0) g_part[blockIdx.x] = sh[0];
}

__global__ void k_scanB() {
    int run = 0;
    for (int b = 0; b < SCB; b++) { int v = g_part[b]; g_part[b] = run; run += v; }
    g_rowptr[N_NODES] = run;
}

__global__ void k_scanC() {
    __shared__ int sh[1024];
    int t = threadIdx.x;
    int idx = blockIdx.x * 1024 + t;
    int v = (idx < N_NODES) ? g_indeg[idx] : 0;
    sh[t] = v;
    __syncthreads();
    for (int off = 1; off < 1024; off <<= 1) {
        int x = (t >= off) ? sh[t - off] : 0;
        __syncthreads();
        sh[t] += x;
        __syncthreads();
    }
    if (idx < N_NODES) g_rowptr[idx] = g_part[blockIdx.x] + sh[t] - v;
}

__global__ void k_csrfill(const int* __restrict__ dst) {
    int e = blockIdx.x * blockDim.x + threadIdx.x;
    if (e < N_EDGES) {
        int d = dst[e];
        int pos = g_rowptr[d] + atomicAdd(&g_cursor[d], 1);
        g_csr[pos] = e;
    }
}

__global__ void k_csrdata(const int* __restrict__ src, const int* __restrict__ dst,
                          const float* __restrict__ ef) {
    int idx = blockIdx.x * blockDim.x + threadIdx.x;
    if (idx < N_EDGES) {
        int eid = g_csr[idx];
        int s = src[eid];
        g_csrc[idx] = s;
        g_enorm[idx] = rsqrtf(g_deg[s] * g_deg[dst[eid]]);
    }
    if (idx < N_EDGES * FE) {
        int pos = idx >> 4, k = idx & 15;
        g_cef[idx] = ef[(size_t)g_csr[pos] * FE + k];
    }
}

__global__ void k_gscan() {
    __shared__ int sh[1024];
    int t = threadIdx.x;
    int b4 = t * 4;
    int a0 = g_gcnt[b4], a1 = g_gcnt[b4 + 1], a2 = g_gcnt[b4 + 2], a3 = g_gcnt[b4 + 3];
    int s = a0 + a1 + a2 + a3;
    sh[t] = s;
    __syncthreads();
    for (int off = 1; off < 1024; off <<= 1) {
        int v = (t >= off) ? sh[t - off] : 0;
        __syncthreads();
        sh[t] += v;
        __syncthreads();
    }
    int excl = sh[t] - s;
    g_grow[b4] = excl;
    g_grow[b4 + 1] = excl + a0;
    g_grow[b4 + 2] = excl + a0 + a1;
    g_grow[b4 + 3] = excl + a0 + a1 + a2;
    if (t == 1023) g_grow[BGRAPH] = sh[1023];
}

// ---------------- virtual-node segment sum -> vtmp split planes ----------------
__global__ void k_vsum() {
    int b = blockIdx.x;
    int j = threadIdx.x;
    if (j >= H) return;
    int r0 = g_grow[b], r1 = g_grow[b + 1];
    float s = 0.f;
    for (int n = r0; n < r1; n++) s += g_x[(size_t)n * H + j];
    float v = s + (float)(r1 - r0 + 1) * g_vfeat[(size_t)b * H + j];
    unsigned short h, m, lo;
    split3(v, h, m, lo);
    size_t o = (size_t)b * VTSTR + j;
    g_vth[o] = h; g_vtm[o] = m; g_vtl[o] = lo;
}

// ---------------- split3-bf16 GEMM: 128x160, 2-stage cp.async (R13) ------------
__device__ __forceinline__ void mma_bf16(float* c, uint32_t a0, uint32_t a1,
                                         uint32_t a2, uint32_t a3,
                                         uint32_t b0, uint32_t b1) {
    asm volatile(
        "mma.sync.aligned.m16n8k16.row.col.f32.bf16.bf16.f32 "
        "{%0,%1,%2,%3}, {%4,%5,%6,%7}, {%8,%9}, {%0,%1,%2,%3};"
        : "+f"(c[0]), "+f"(c[1]), "+f"(c[2]), "+f"(c[3])
        : "r"(a0), "r"(a1), "r"(a2), "r"(a3), "r"(b0), "r"(b1));
}

#define CP16(dst, src) \
    asm volatile("cp.async.ca.shared.global [%0], [%1], 16;" :: "r"(dst), "l"(src))
#define CP_COMMIT() asm volatile("cp.async.commit_group;")
#define CP_WAIT1()  asm volatile("cp.async.wait_group 1;")
#define CP_WAIT0()  asm volatile("cp.async.wait_group 0;")

#define STG_U32 10368
#define GEMM_SMEM (2 * STG_U32 * 4)   // 82944 bytes

__global__ __launch_bounds__(256)
void k_gemm_t(const uint32_t* __restrict__ Ah, const uint32_t* __restrict__ Am,
              const uint32_t* __restrict__ Al, int aStr,
              const uint32_t* __restrict__ Bh, const uint32_t* __restrict__ Bm,
              const uint32_t* __restrict__ Bl, int bStr,
              const float* __restrict__ bias, float* __restrict__ C,
              int M, int Ncol, int nkt) {
    extern __shared__ uint32_t sm[];
    uint32_t sbase = (uint32_t)__cvta_generic_to_shared(sm);

    int tid = threadIdx.x;
    int warp = tid >> 5, lane = tid & 31;
    int wm = warp >> 2, wn = warp & 3;
    int m0 = blockIdx.y * 128, n0 = blockIdx.x * 160;
    int lg = lane >> 2, lt = lane & 3;

    float acc[4][5][4];
#pragma unroll
    for (int i = 0; i < 4; i++)
#pragma unroll
        for (int j = 0; j < 5; j++)
#pragma unroll
            for (int c = 0; c < 4; c++) acc[i][j][c] = 0.f;

    auto issue = [&](int kt, int stg) {
        uint32_t sb = sbase + stg * (STG_U32 * 4);
        int p0 = kt * 8;
#pragma unroll
        for (int i = 0; i < 3; i++) {
            int c = tid + 256 * i;
            int pl = c >> 8, rr = (c >> 1) & 127, hf = c & 1;
            const uint32_t* ap = (pl == 0) ? Ah : (pl == 1) ? Am : Al;
            const uint32_t* s = ap + (size_t)(m0 + rr) * aStr + p0 + hf * 4;
            uint32_t d = sb + (pl * 1536 + rr * 12 + hf * 4) * 4;
            CP16(d, s);
        }
#pragma unroll
        for (int i = 0; i < 4; i++) {
            int c = tid + 256 * i;
            if (c < 960) {
                int pl = c / 320, rem = c % 320, nn = rem >> 1, hf = rem & 1;
                const uint32_t* bp = (pl == 0) ? Bh : (pl == 1) ? Bm : Bl;
                const uint32_t* s = bp + (size_t)(n0 + nn) * bStr + p0 + hf * 4;
                uint32_t d = sb + (4608 + pl * 1920 + nn * 12 + hf * 4) * 4;
                CP16(d, s);
            }
        }
        CP_COMMIT();
    };

    issue(0, 0);

    for (int kt = 0; kt < nkt; kt++) {
        if (kt + 1 < nkt) {
            issue(kt + 1, (kt + 1) & 1);
            CP_WAIT1();
        } else {
            CP_WAIT0();
        }
        __syncthreads();

        const uint32_t* st = sm + (kt & 1) * STG_U32;
        const uint32_t* sAh = st;
        const uint32_t* sAm = st + 1536;
        const uint32_t* sAl = st + 3072;
        const uint32_t* sBh = st + 4608;
        const uint32_t* sBm = st + 6528;
        const uint32_t* sBl = st + 8448;

        uint32_t bh[5][2], bm[5][2], bl[5][2];
#pragma unroll
        for (int nt = 0; nt < 5; nt++) {
            int bn2 = (wn * 40 + nt * 8 + lg) * 12;
            bh[nt][0] = sBh[bn2 + lt]; bh[nt][1] = sBh[bn2 + 4 + lt];
            bm[nt][0] = sBm[bn2 + lt]; bm[nt][1] = sBm[bn2 + 4 + lt];
            bl[nt][0] = sBl[bn2 + lt]; bl[nt][1] = sBl[bn2 + 4 + lt];
        }
#pragma unroll
        for (int mt = 0; mt < 4; mt++) {
            int am = (wm * 64 + mt * 16 + lg) * 12;
            int am8 = am + 8 * 12;
            uint32_t ah0 = sAh[am + lt],      ah1 = sAh[am8 + lt];
            uint32_t ah2 = sAh[am + 4 + lt],  ah3 = sAh[am8 + 4 + lt];
            uint32_t amd0 = sAm[am + lt],     amd1 = sAm[am8 + lt];
            uint32_t amd2 = sAm[am + 4 + lt], amd3 = sAm[am8 + 4 + lt];
            uint32_t alo0 = sAl[am + lt],     alo1 = sAl[am8 + lt];
            uint32_t alo2 = sAl[am + 4 + lt], alo3 = sAl[am8 + 4 + lt];
#pragma unroll
            for (int nt = 0; nt < 5; nt++) {
                mma_bf16(acc[mt][nt], ah0, ah1, ah2, ah3, bh[nt][0], bh[nt][1]);
                mma_bf16(acc[mt][nt], ah0, ah1, ah2, ah3, bm[nt][0], bm[nt][1]);
                mma_bf16(acc[mt][nt], amd0, amd1, amd2, amd3, bh[nt][0], bh[nt][1]);
                mma_bf16(acc[mt][nt], ah0, ah1, ah2, ah3, bl[nt][0], bl[nt][1]);
                mma_bf16(acc[mt][nt], alo0, alo1, alo2, alo3, bh[nt][0], bh[nt][1]);
                mma_bf16(acc[mt][nt], amd0, amd1, amd2, amd3, bm[nt][0], bm[nt][1]);
            }
        }
        __syncthreads();
    }

    // writeout
#pragma unroll
    for (int mt = 0; mt < 4; mt++) {
#pragma unroll
        for (int nt = 0; nt < 5; nt++) {
            int gn = n0 + wn * 40 + nt * 8 + 2 * lt;
            if (gn >= Ncol) continue;
            float b0 = bias[gn], b1 = bias[gn + 1];
            int gm0 = m0 + wm * 64 + mt * 16 + lg;
            if (gm0 < M) {
                float2 o = make_float2(acc[mt][nt][0] + b0, acc[mt][nt][1] + b1);
                *(float2*)(C + (size_t)gm0 * Ncol + gn) = o;
            }
            int gm1 = gm0 + 8;
            if (gm1 < M) {
                float2 o = make_float2(acc[mt][nt][2] + b0, acc[mt][nt][3] + b1);
                *(float2*)(C + (size_t)gm1 * Ncol + gn) = o;
            }
        }
    }
}

// ---------------- node aggregation: column-slice + 1-deep edge prefetch --------
__global__ __launch_bounds__(320)
void k_agg(const float* __restrict__ be_l, const float* __restrict__ We_l,
           const float* __restrict__ res_l) {
    int tid = threadIdx.x;
    int lane = tid & 31;
    int j = tid;
    bool act = (j < H);

    float wj[16];
#pragma unroll
    for (int k = 0; k < 16; k++) wj[k] = act ? We_l[k * H + j] : 0.f;
    float bj = act ? be_l[j] : 0.f;
    float rj = act ? res_l[j] : 0.f;

    float ls = 0.f, lq = 0.f;

    for (int n = blockIdx.x; n < N_NODES; n += gridDim.x) {
        float dn = g_deg[n];
        float a = act ? fmaxf(g_hp[(size_t)n * H + j] + rj, 0.f) / dn : 0.f;
        int e0 = g_rowptr[n], e1 = g_rowptr[n + 1];
        if (e0 < e1) {
            float nrmc = g_enorm[e0];
            float evc = (lane < FE) ? g_cef[(size_t)e0 * FE + lane] : 0.f;
            float hvc = act ? g_hp[(size_t)g_csrc[e0] * H + j] : 0.f;
            for (int e = e0; e < e1; e++) {
                float nrmn = 0.f, evn = 0.f, hvn = 0.f;
                if (e + 1 < e1) {
                    nrmn = g_enorm[e + 1];
                    evn = (lane < FE) ? g_cef[(size_t)(e + 1) * FE + lane] : 0.f;
                    hvn = act ? g_hp[(size_t)g_csrc[e + 1] * H + j] : 0.f;
                }
                float ep = bj;
#pragma unroll
                for (int k = 0; k < 16; k++)
                    ep = fmaf(__shfl_sync(0xffffffffu, evc, k), wj[k], ep);
                if (act) a += nrmc * fmaxf(hvc + ep, 0.f);
                nrmc = nrmn; evc = evn; hvc = hvn;
            }
        }
        if (act) {
            g_acc[(size_t)n * H + j] = a;
            ls += a;
            lq += a * a;
        }
    }
    if (act) {
        atomicAdd(&g_sum[j], ls);
        atomicAdd(&g_sumsq[j], lq);
    }
}

// ---------------- batch norm (R13 style: separate final) -----------------------

__global__ void k_zero_stats(float* __restrict__ sum, float* __restrict__ sumsq,
                             int cols) {
    int c = blockIdx.x * blockDim.x + threadIdx.x;
    if (c < cols) { sum[c] = 0.0f; sumsq[c] = 0.0f; }
}

__global__ void k_bnstat(const float* __restrict__ X, int rows, int cols,
                         float* __restrict__ sum, float* __restrict__ sumsq) {
    int r0 = blockIdx.x * 256;
    int rend = min(r0 + 256, rows);
    int t = threadIdx.x;
    float s[3] = {0, 0, 0}, q[3] = {0, 0, 0};
    for (int r = r0; r < rend; r++) {
        const float* row = X + (size_t)r * cols;
        int ci = 0;
        for (int c = t; c < cols; c += 256, ci++) {
            float v = row[c];
            s[ci] += v; q[ci] += v * v;
        }
    }
    int ci = 0;
    for (int c = t; c < cols; c += 256, ci++) {
        atomicAdd(&sum[c], s[ci]);
        atomicAdd(&sumsq[c], q[ci]);
    }
}

__global__ void k_bnfinal(int rows, int cols,
                          const float* __restrict__ sum,
                          const float* __restrict__ sumsq,
                          float* __restrict__ mean, float* __restrict__ rstd) {
    int c = blockIdx.x * blockDim.x + threadIdx.x;
    if (c < cols) {
        float m = sum[c] / (float)rows;
        float v = sumsq[c] / (float)rows - m * m;
        mean[c] = m;
        rstd[c] = rsqrtf(v + BN_EPS);
    }
}

__global__ void k_bnap(const float* __restrict__ X, float* __restrict__ Y,
                       const float* __restrict__ gamma,
                       const float* __restrict__ beta,
                       const float* __restrict__ mean,
                       const float* __restrict__ rstd,
                       int rows, int cols, int do_relu,
                       unsigned short* __restrict__ ph,
                       unsigned short* __restrict__ pm,
                       unsigned short* __restrict__ pl,
                       int pstride,
                       const int* __restrict__ gid,
                       const float* __restrict__ vfeat) {
    int idx = blockIdx.x * blockDim.x + threadIdx.x;
    if (idx < rows * cols) {
        int r = idx / cols, c = idx - r * cols;
        float v = (X[idx] - mean[c]) * rstd[c] * gamma[c] + beta[c];
        if (do_relu) v = fmaxf(v, 0.0f);
        if (Y) Y[idx] = v;
        if (ph) {
            float p = v;
            if (gid) p += vfeat[(size_t)gid[r] * cols + c];
            unsigned short h, m, lo;
            split3(p, h, m, lo);
            size_t o = (size_t)r * pstride + c;
            ph[o] = h; pm[o] = m; pl[o] = lo;
        }
    }
}

// ---------------- host orchestration -------------------------------------------

extern "C" void kernel_launch(void* const* d_in, const int* in_sizes, int n_in,
                              void* d_out, int out_size) {
    const int *node_types, *src, *dst, *gid;
    const float *edge_feats, *node_emb, *Wn, *bn_lin, *We, *be, *res_emb,
                *bn_gamma, *bn_beta, *vn_emb, *vW1, *vb1, *vg1, *vbt1,
                *vW2, *vb2, *vg2, *vbt2;

    if (in_sizes[0] == N_NODES) {
        node_types = (const int*)d_in[0];
        edge_feats = (const float*)d_in[1];
        src        = (const int*)d_in[2];
        dst        = (const int*)d_in[3];
        gid        = (const int*)d_in[4];
        node_emb = (const float*)d_in[6];
        Wn       = (const float*)d_in[7];
        bn_lin   = (const float*)d_in[8];
        We       = (const float*)d_in[9];
        be       = (const float*)d_in[10];
        res_emb  = (const float*)d_in[11];
        bn_gamma = (const float*)d_in[12];
        bn_beta  = (const float*)d_in[13];
        vn_emb   = (const float*)d_in[14];
        vW1  = (const float*)d_in[15];
        vb1  = (const float*)d_in[16];
        vg1  = (const float*)d_in[17];
        vbt1 = (const float*)d_in[18];
        vW2  = (const float*)d_in[19];
        vb2  = (const float*)d_in[20];
        vg2  = (const float*)d_in[21];
        vbt2 = (const float*)d_in[22];
    } else {
        edge_feats = (const float*)d_in[0];
        node_emb = (const float*)d_in[1];
        Wn       = (const float*)d_in[2];
        bn_lin   = (const float*)d_in[3];
        We       = (const float*)d_in[4];
        be       = (const float*)d_in[5];
        res_emb  = (const float*)d_in[6];
        bn_gamma = (const float*)d_in[7];
        bn_beta  = (const float*)d_in[8];
        vn_emb   = (const float*)d_in[9];
        vW1  = (const float*)d_in[10];
        vb1  = (const float*)d_in[11];
        vg1  = (const float*)d_in[12];
        vbt1 = (const float*)d_in[13];
        vW2  = (const float*)d_in[14];
        vb2  = (const float*)d_in[15];
        vg2  = (const float*)d_in[16];
        vbt2 = (const float*)d_in[17];
        node_types = (const int*)d_in[18];
        src        = (const int*)d_in[19];
        dst        = (const int*)d_in[20];
        gid        = (const int*)d_in[21];
    }

    const int NH = N_NODES * H;
    const int BH = BGRAPH * H;
    const int TPB = 256;

    float *g_x_p, *g_hp_p, *g_acc_p, *g_vtmp_p, *g_vfeat_p, *g_z1_p;
    cudaGetSymbolAddress((void**)&g_x_p, g_x);
    cudaGetSymbolAddress((void**)&g_hp_p, g_hp);
    cudaGetSymbolAddress((void**)&g_acc_p, g_acc);
    cudaGetSymbolAddress((void**)&g_vtmp_p, g_vtmp);
    cudaGetSymbolAddress((void**)&g_vfeat_p, g_vfeat);
    cudaGetSymbolAddress((void**)&g_z1_p, g_z1);
    float *sum_p, *sq_p, *mean_p, *rstd_p, *vsum_p, *vsq_p, *vmean_p, *vrstd_p;
    cudaGetSymbolAddress((void**)&sum_p, g_sum);
    cudaGetSymbolAddress((void**)&sq_p, g_sumsq);
    cudaGetSymbolAddress((void**)&mean_p, g_mean);
    cudaGetSymbolAddress((void**)&rstd_p, g_rstd);
    cudaGetSymbolAddress((void**)&vsum_p, g_vsumB);
    cudaGetSymbolAddress((void**)&vsq_p, g_vsqB);
    cudaGetSymbolAddress((void**)&vmean_p, g_vmeanB);
    cudaGetSymbolAddress((void**)&vrstd_p, g_vrstdB);
    unsigned short *ah_p, *am_p, *al_p, *vth_p, *vtm_p, *vtl_p,
                   *z1h_p, *z1m_p, *z1l_p, *wh_p, *wm_p, *wl_p;
    cudaGetSymbolAddress((void**)&ah_p, g_ah);
    cudaGetSymbolAddress((void**)&am_p, g_am2);
    cudaGetSymbolAddress((void**)&al_p, g_al);
    cudaGetSymbolAddress((void**)&vth_p, g_vth);
    cudaGetSymbolAddress((void**)&vtm_p, g_vtm);
    cudaGetSymbolAddress((void**)&vtl_p, g_vtl);
    cudaGetSymbolAddress((void**)&z1h_p, g_z1h);
    cudaGetSymbolAddress((void**)&z1m_p, g_z1m);
    cudaGetSymbolAddress((void**)&z1l_p, g_z1l);
    cudaGetSymbolAddress((void**)&wh_p, g_wh);
    cudaGetSymbolAddress((void**)&wm_p, g_wm);
    cudaGetSymbolAddress((void**)&wl_p, g_wl);
    const uint32_t* Ah = (const uint32_t*)ah_p;
    const uint32_t* Am = (const uint32_t*)am_p;
    const uint32_t* Al = (const uint32_t*)al_p;
    const uint32_t* VTh = (const uint32_t*)vth_p;
    const uint32_t* VTm = (const uint32_t*)vtm_p;
    const uint32_t* VTl = (const uint32_t*)vtl_p;
    const uint32_t* Z1h = (const uint32_t*)z1h_p;
    const uint32_t* Z1m = (const uint32_t*)z1m_p;
    const uint32_t* Z1l = (const uint32_t*)z1l_p;

    cudaFuncSetAttribute(k_gemm_t, cudaFuncAttributeMaxDynamicSharedMemorySize,
                         GEMM_SMEM);

    static cudaStream_t s2 = nullptr;
    static cudaEvent_t ev_fork = nullptr, ev_join = nullptr;
    if (!s2) {
        cudaStreamCreateWithFlags(&s2, cudaStreamNonBlocking);
        cudaEventCreateWithFlags(&ev_fork, cudaEventDisableTiming);
        cudaEventCreateWithFlags(&ev_join, cudaEventDisableTiming);
    }

    k_init0<<<cdiv(WTOTP, TPB), TPB>>>(Wn, vW1, vW2);
    k_count<<<cdiv(N_EDGES, TPB), TPB>>>(dst, gid);
    k_init3<<<cdiv(NH, TPB), TPB>>>(node_emb, node_types, vn_emb);
    k_gscan<<<1, 1024>>>();

    dim3 node_grid(2, AROWS / 128);

    for (int l = 0; l < LAYERS; l++) {
        const float* bnl_l = bn_lin + l * H;
        const float* We_l  = We + (size_t)l * FE * H;
        const float* be_l  = be + l * H;
        const float* res_l = res_emb + l * H;
        const float* gam_l = bn_gamma + l * H;
        const float* bet_l = bn_beta + l * H;
        const uint32_t* Wnh = (const uint32_t*)(wh_p + WNP_BASE + (size_t)l * WNP_SEG);
        const uint32_t* Wnm = (const uint32_t*)(wm_p + WNP_BASE + (size_t)l * WNP_SEG);
        const uint32_t* Wnl = (const uint32_t*)(wl_p + WNP_BASE + (size_t)l * WNP_SEG);

        bool has_vn = (l < LAYERS - 1);

        if (has_vn) {
            const float* vb1_l  = vb1 + l * H2;
            const float* vg1_l  = vg1 + l * H2;
            const float* vbt1_l = vbt1 + l * H2;
            const float* vb2_l  = vb2 + l * H;
            const float* vg2_l  = vg2 + l * H;
            const float* vbt2_l = vbt2 + l * H;
            const uint32_t* W1h = (const uint32_t*)(wh_p + VW1P_BASE + (size_t)l * VW1P_SEG);
            const uint32_t* W1m = (const uint32_t*)(wm_p + VW1P_BASE + (size_t)l * VW1P_SEG);
            const uint32_t* W1l = (const uint32_t*)(wl_p + VW1P_BASE + (size_t)l * VW1P_SEG);
            const uint32_t* W2h = (const uint32_t*)(wh_p + VW2P_BASE + (size_t)l * VW2P_SEG);
            const uint32_t* W2m = (const uint32_t*)(wm_p + VW2P_BASE + (size_t)l * VW2P_SEG);
            const uint32_t* W2l = (const uint32_t*)(wl_p + VW2P_BASE + (size_t)l * VW2P_SEG);

            cudaEventRecord(ev_fork, 0);
            cudaStreamWaitEvent(s2, ev_fork, 0);

            k_vsum<<<BGRAPH, 320, 0, s2>>>();
            dim3 g1(4, BGRAPH / 128);
            k_gemm_t<<<g1, 256, GEMM_SMEM, s2>>>(VTh, VTm, VTl, 152,
                                                 W1h, W1m, W1l, 152,
                                                 vb1_l, g_z1_p, BGRAPH, H2, 19);
            k_zero_stats<<<cdiv(H2, TPB), TPB, 0, s2>>>(vsum_p, vsq_p, H2);
            k_bnstat<<<cdiv(BGRAPH, 256), 256, 0, s2>>>(g_z1_p, BGRAPH, H2,
                                                        vsum_p, vsq_p);
            k_bnfinal<<<cdiv(H2, TPB), TPB, 0, s2>>>(BGRAPH, H2, vsum_p, vsq_p,
                                                     vmean_p, vrstd_p);
            k_bnap<<<cdiv(BGRAPH * H2, TPB), TPB, 0, s2>>>(
                g_z1_p, nullptr, vg1_l, vbt1_l, vmean_p, vrstd_p,
                BGRAPH, H2, 1, z1h_p, z1m_p, z1l_p, Z1STR, nullptr, nullptr);

            dim3 g2(2, BGRAPH / 128);
            k_gemm_t<<<g2, 256, GEMM_SMEM, s2>>>(Z1h, Z1m, Z1l, 304,
                                                 W2h, W2m, W2l, 304,
                                                 vb2_l, g_vtmp_p, BGRAPH, H, 38);
            k_zero_stats<<<cdiv(H, TPB), TPB, 0, s2>>>(vsum_p, vsq_p, H);
            k_bnstat<<<cdiv(BGRAPH, 256), 256, 0, s2>>>(g_vtmp_p, BGRAPH, H,
                                                        vsum_p, vsq_p);
            k_bnfinal<<<cdiv(H, TPB), TPB, 0, s2>>>(BGRAPH, H, vsum_p, vsq_p,
                                                    vmean_p, vrstd_p);
            k_bnap<<<cdiv(BH, TPB), TPB, 0, s2>>>(
                g_vtmp_p, g_vfeat_p, vg2_l, vbt2_l, vmean_p, vrstd_p,
                BGRAPH, H, 1, nullptr, nullptr, nullptr, 0, nullptr, nullptr);

            cudaEventRecord(ev_join, s2);
        }

        k_gemm_t<<<node_grid, 256, GEMM_SMEM>>>(Ah, Am, Al, 152,
                                                Wnh, Wnm, Wnl, 152,
                                                bnl_l, g_hp_p, N_NODES, H, 19);

        if (l == 0) {
            k_scanA<<<SCB, 1024>>>();
            k_scanB<<<1, 1>>>();
            k_scanC<<<SCB, 1024>>>();
            k_csrfill<<<cdiv(N_EDGES, TPB), TPB>>>(dst);
            k_csrdata<<<cdiv(N_EDGES * FE, TPB), TPB>>>(src, dst, edge_feats);
        }

        k_zero_stats<<<cdiv(H, TPB), TPB>>>(sum_p, sq_p, H);
        k_agg<<<888, 320>>>(be_l, We_l, res_l);
        k_bnfinal<<<cdiv(H, TPB), TPB>>>(N_NODES, H, sum_p, sq_p, mean_p, rstd_p);

        if (has_vn) {
            cudaStreamWaitEvent(0, ev_join, 0);
            k_bnap<<<cdiv(NH, TPB), TPB>>>(g_acc_p, g_x_p, gam_l, bet_l,
                                           mean_p, rstd_p, N_NODES, H, 1,
                                           ah_p, am_p, al_p, ASTR,
                                           gid, g_vfeat_p);
        } else {
            k_bnap<<<cdiv(NH, TPB), TPB>>>(g_acc_p, (float*)d_out, gam_l, bet_l,
                                           mean_p, rstd_p, N_NODES, H, 0,
                                           nullptr, nullptr, nullptr, 0,
                                           nullptr, nullptr);
        }
    }
}

// round 17
// speedup vs baseline: 1.2505x; 1.1345x over previous
#include <cuda_runtime.h>
#include <cuda_bf16.h>
#include <cstdint>
#include <math.h>

#define N_NODES 100000
#define N_EDGES 260000
#define BGRAPH  4096
#define H       300
#define H2      600
#define LAYERS  5
#define FE      16
#define BN_EPS  1e-5f
#define SCB     ((N_NODES + 1023) / 1024)

// padded plane geometry (ushort elements)
#define AROWS   100096
#define ASTR    304
#define VTSTR   304
#define Z1STR   608
#define WNP_SEG  (320 * 304)
#define VW1P_SEG (640 * 304)
#define VW2P_SEG (320 * 608)
#define WNP_BASE  0
#define VW1P_BASE (LAYERS * WNP_SEG)
#define VW2P_BASE (VW1P_BASE + (LAYERS - 1) * VW1P_SEG)
#define WTOTP     (VW2P_BASE + (LAYERS - 1) * VW2P_SEG)
#define PADA      (AROWS * 4)

// ---------------- device scratch -----------------------------------------------
__device__ float g_x[N_NODES * H];
__device__ float g_hp[N_NODES * H];
__device__ float g_acc[N_NODES * H];
__device__ float g_deg[N_NODES];
__device__ int   g_indeg[N_NODES];
__device__ int   g_cursor[N_NODES];
__device__ int   g_rowptr[N_NODES + 1];
__device__ int   g_part[SCB];
__device__ int   g_csr[N_EDGES];
__device__ int   g_csrc[N_EDGES];
__device__ float g_enorm[N_EDGES];
__device__ float g_cef[N_EDGES * FE];
__device__ int   g_gcnt[BGRAPH];
__device__ int   g_grow[BGRAPH + 1];
__device__ float g_vfeat[BGRAPH * H];
__device__ float g_vtmp[BGRAPH * H];
__device__ float g_z1[BGRAPH * H2];
__device__ float g_sum[H2];
__device__ float g_sumsq[H2];
__device__ float g_mean[H2];
__device__ float g_rstd[H2];
__device__ float g_vsumB[H2];
__device__ float g_vsqB[H2];
__device__ float g_vmeanB[H2];
__device__ float g_vrstdB[H2];
__device__ unsigned short g_ah[AROWS * ASTR];
__device__ unsigned short g_am2[AROWS * ASTR];
__device__ unsigned short g_al[AROWS * ASTR];
__device__ unsigned short g_vth[BGRAPH * VTSTR];
__device__ unsigned short g_vtm[BGRAPH * VTSTR];
__device__ unsigned short g_vtl[BGRAPH * VTSTR];
__device__ unsigned short g_z1h[BGRAPH * Z1STR];
__device__ unsigned short g_z1m[BGRAPH * Z1STR];
__device__ unsigned short g_z1l[BGRAPH * Z1STR];
__device__ unsigned short g_wh[WTOTP];
__device__ unsigned short g_wm[WTOTP];
__device__ unsigned short g_wl[WTOTP];

static inline int cdiv(int a, int b) { return (a + b - 1) / b; }

__device__ __forceinline__ void split3(float v, unsigned short& h,
                                       unsigned short& m, unsigned short& l) {
    __nv_bfloat16 hb = __float2bfloat16(v);
    float r1 = v - __bfloat162float(hb);
    __nv_bfloat16 mb = __float2bfloat16(r1);
    float r2 = r1 - __bfloat162float(mb);
    __nv_bfloat16 lb = __float2bfloat16(r2);
    h = __bfloat16_as_ushort(hb);
    m = __bfloat16_as_ushort(mb);
    l = __bfloat16_as_ushort(lb);
}

// ---------------- init ----------------------------------------------------------
__global__ void k_init0(const float* __restrict__ Wn,
                        const float* __restrict__ vW1,
                        const float* __restrict__ vW2) {
    int i = blockIdx.x * blockDim.x + threadIdx.x;
    if (i < N_NODES) { g_indeg[i] = 0; g_cursor[i] = 0; }
    if (i < BGRAPH) g_gcnt[i] = 0;
    if (i < WTOTP) {
        float v = 0.f;
        if (i < VW1P_BASE) {
            int l = i / WNP_SEG, r = i % WNP_SEG;
            int n = r / 304, k = r % 304;
            if (n < H && k < H) v = Wn[(size_t)l * H * H + k * H + n];
        } else if (i < VW2P_BASE) {
            int e = i - VW1P_BASE;
            int l = e / VW1P_SEG, r = e % VW1P_SEG;
            int n = r / 304, k = r % 304;
            if (n < H2 && k < H) v = vW1[(size_t)l * H * H2 + k * H2 + n];
        } else {
            int e = i - VW2P_BASE;
            int l = e / VW2P_SEG, r = e % VW2P_SEG;
            int n = r / 608, k = r % 608;
            if (n < H && k < H2) v = vW2[(size_t)l * H2 * H + k * H + n];
        }
        unsigned short h, m, lo;
        split3(v, h, m, lo);
        g_wh[i] = h; g_wm[i] = m; g_wl[i] = lo;
    }
    if (i < PADA) {
        size_t o = (size_t)(i >> 2) * ASTR + 300 + (i & 3);
        g_ah[o] = 0; g_am2[o] = 0; g_al[o] = 0;
    }
    if (i < 96 * ASTR) {
        size_t o = (size_t)(N_NODES + i / ASTR) * ASTR + (i % ASTR);
        g_ah[o] = 0; g_am2[o] = 0; g_al[o] = 0;
    }
    if (i < BGRAPH * 4) {
        size_t o = (size_t)(i >> 2) * VTSTR + 300 + (i & 3);
        g_vth[o] = 0; g_vtm[o] = 0; g_vtl[o] = 0;
    }
    if (i < BGRAPH * 8) {
        size_t o = (size_t)(i >> 3) * Z1STR + 600 + (i & 7);
        g_z1h[o] = 0; g_z1m[o] = 0; g_z1l[o] = 0;
    }
}

__global__ void k_count(const int* __restrict__ dst, const int* __restrict__ gid) {
    int i = blockIdx.x * blockDim.x + threadIdx.x;
    if (i < N_EDGES) atomicAdd(&g_indeg[dst[i]], 1);
    if (i < N_NODES) atomicAdd(&g_gcnt[gid[i]], 1);
}

__global__ void k_init3(const float* __restrict__ node_emb,
                        const int* __restrict__ node_types,
                        const float* __restrict__ vn_emb) {
    int idx = blockIdx.x * blockDim.x + threadIdx.x;
    if (idx < N_NODES * H) {
        int n = idx / H, j = idx - n * H;
        float hv = node_emb[node_types[n] * H + j];
        g_x[idx] = hv;
        unsigned short h, m, lo;
        split3(hv + vn_emb[j], h, m, lo);
        size_t o = (size_t)n * ASTR + j;
        g_ah[o] = h; g_am2[o] = m; g_al[o] = lo;
    }
    if (idx < BGRAPH * H) g_vfeat[idx] = vn_emb[idx % H];
    if (idx < N_NODES) g_deg[idx] = (float)g_indeg[idx] + 1.0f;
}

// ---------------- CSR build ----------------------------------------------------

__global__ void k_scanA() {
    __shared__ int sh[1024];
    int t = threadIdx.x;
    int idx = blockIdx.x * 1024 + t;
    sh[t] = (idx < N_NODES) ? g_indeg[idx] : 0;
    __syncthreads();
    for (int s = 512; s > 0; s >>= 1) {
        if (t < s) sh[t] += sh[t + s];
        __syncthreads();
    }
    if (t == 0) g_part[blockIdx.x] = sh[0];
}

__global__ void k_scanB() {
    int run = 0;
    for (int b = 0; b < SCB; b++) { int v = g_part[b]; g_part[b] = run; run += v; }
    g_rowptr[N_NODES] = run;
}

__global__ void k_scanC() {
    __shared__ int sh[1024];
    int t = threadIdx.x;
    int idx = blockIdx.x * 1024 + t;
    int v = (idx < N_NODES) ? g_indeg[idx] : 0;
    sh[t] = v;
    __syncthreads();
    for (int off = 1; off < 1024; off <<= 1) {
        int x = (t >= off) ? sh[t - off] : 0;
        __syncthreads();
        sh[t] += x;
        __syncthreads();
    }
    if (idx < N_NODES) g_rowptr[idx] = g_part[blockIdx.x] + sh[t] - v;
}

__global__ void k_csrfill(const int* __restrict__ dst) {
    int e = blockIdx.x * blockDim.x + threadIdx.x;
    if (e < N_EDGES) {
        int d = dst[e];
        int pos = g_rowptr[d] + atomicAdd(&g_cursor[d], 1);
        g_csr[pos] = e;
    }
}

__global__ void k_csrdata(const int* __restrict__ src, const int* __restrict__ dst,
                          const float* __restrict__ ef) {
    int idx = blockIdx.x * blockDim.x + threadIdx.x;
    if (idx < N_EDGES) {
        int eid = g_csr[idx];
        int s = src[eid];
        g_csrc[idx] = s;
        g_enorm[idx] = rsqrtf(g_deg[s] * g_deg[dst[eid]]);
    }
    if (idx < N_EDGES * FE) {
        int pos = idx >> 4, k = idx & 15;
        g_cef[idx] = ef[(size_t)g_csr[pos] * FE + k];
    }
}

__global__ void k_gscan() {
    __shared__ int sh[1024];
    int t = threadIdx.x;
    int b4 = t * 4;
    int a0 = g_gcnt[b4], a1 = g_gcnt[b4 + 1], a2 = g_gcnt[b4 + 2], a3 = g_gcnt[b4 + 3];
    int s = a0 + a1 + a2 + a3;
    sh[t] = s;
    __syncthreads();
    for (int off = 1; off < 1024; off <<= 1) {
        int v = (t >= off) ? sh[t - off] : 0;
        __syncthreads();
        sh[t] += v;
        __syncthreads();
    }
    int excl = sh[t] - s;
    g_grow[b4] = excl;
    g_grow[b4 + 1] = excl + a0;
    g_grow[b4 + 2] = excl + a0 + a1;
    g_grow[b4 + 3] = excl + a0 + a1 + a2;
    if (t == 1023) g_grow[BGRAPH] = sh[1023];
}

// ---------------- virtual-node segment sum -> vtmp split planes ----------------
__global__ void k_vsum() {
    int b = blockIdx.x;
    int j = threadIdx.x;
    if (j >= H) return;
    int r0 = g_grow[b], r1 = g_grow[b + 1];
    float s = 0.f;
    for (int n = r0; n < r1; n++) s += g_x[(size_t)n * H + j];
    float v = s + (float)(r1 - r0 + 1) * g_vfeat[(size_t)b * H + j];
    unsigned short h, m, lo;
    split3(v, h, m, lo);
    size_t o = (size_t)b * VTSTR + j;
    g_vth[o] = h; g_vtm[o] = m; g_vtl[o] = lo;
}

// ---------------- split3-bf16 GEMM: 128x160, 2-stage cp.async (R13) ------------
__device__ __forceinline__ void mma_bf16(float* c, uint32_t a0, uint32_t a1,
                                         uint32_t a2, uint32_t a3,
                                         uint32_t b0, uint32_t b1) {
    asm volatile(
        "mma.sync.aligned.m16n8k16.row.col.f32.bf16.bf16.f32 "
        "{%0,%1,%2,%3}, {%4,%5,%6,%7}, {%8,%9}, {%0,%1,%2,%3};"
        : "+f"(c[0]), "+f"(c[1]), "+f"(c[2]), "+f"(c[3])
        : "r"(a0), "r"(a1), "r"(a2), "r"(a3), "r"(b0), "r"(b1));
}

#define CP16(dst, src) \
    asm volatile("cp.async.ca.shared.global [%0], [%1], 16;" :: "r"(dst), "l"(src))
#define CP_COMMIT() asm volatile("cp.async.commit_group;")
#define CP_WAIT1()  asm volatile("cp.async.wait_group 1;")
#define CP_WAIT0()  asm volatile("cp.async.wait_group 0;")

#define STG_U32 10368
#define GEMM_SMEM (2 * STG_U32 * 4)   // 82944 bytes

__global__ __launch_bounds__(256)
void k_gemm_t(const uint32_t* __restrict__ Ah, const uint32_t* __restrict__ Am,
              const uint32_t* __restrict__ Al, int aStr,
              const uint32_t* __restrict__ Bh, const uint32_t* __restrict__ Bm,
              const uint32_t* __restrict__ Bl, int bStr,
              const float* __restrict__ bias, float* __restrict__ C,
              int M, int Ncol, int nkt) {
    extern __shared__ uint32_t sm[];
    uint32_t sbase = (uint32_t)__cvta_generic_to_shared(sm);

    int tid = threadIdx.x;
    int warp = tid >> 5, lane = tid & 31;
    int wm = warp >> 2, wn = warp & 3;
    int m0 = blockIdx.y * 128, n0 = blockIdx.x * 160;
    int lg = lane >> 2, lt = lane & 3;

    float acc[4][5][4];
#pragma unroll
    for (int i = 0; i < 4; i++)
#pragma unroll
        for (int j = 0; j < 5; j++)
#pragma unroll
            for (int c = 0; c < 4; c++) acc[i][j][c] = 0.f;

    auto issue = [&](int kt, int stg) {
        uint32_t sb = sbase + stg * (STG_U32 * 4);
        int p0 = kt * 8;
#pragma unroll
        for (int i = 0; i < 3; i++) {
            int c = tid + 256 * i;
            int pl = c >> 8, rr = (c >> 1) & 127, hf = c & 1;
            const uint32_t* ap = (pl == 0) ? Ah : (pl == 1) ? Am : Al;
            const uint32_t* s = ap + (size_t)(m0 + rr) * aStr + p0 + hf * 4;
            uint32_t d = sb + (pl * 1536 + rr * 12 + hf * 4) * 4;
            CP16(d, s);
        }
#pragma unroll
        for (int i = 0; i < 4; i++) {
            int c = tid + 256 * i;
            if (c < 960) {
                int pl = c / 320, rem = c % 320, nn = rem >> 1, hf = rem & 1;
                const uint32_t* bp = (pl == 0) ? Bh : (pl == 1) ? Bm : Bl;
                const uint32_t* s = bp + (size_t)(n0 + nn) * bStr + p0 + hf * 4;
                uint32_t d = sb + (4608 + pl * 1920 + nn * 12 + hf * 4) * 4;
                CP16(d, s);
            }
        }
        CP_COMMIT();
    };

    issue(0, 0);

    for (int kt = 0; kt < nkt; kt++) {
        if (kt + 1 < nkt) {
            issue(kt + 1, (kt + 1) & 1);
            CP_WAIT1();
        } else {
            CP_WAIT0();
        }
        __syncthreads();

        const uint32_t* st = sm + (kt & 1) * STG_U32;
        const uint32_t* sAh = st;
        const uint32_t* sAm = st + 1536;
        const uint32_t* sAl = st + 3072;
        const uint32_t* sBh = st + 4608;
        const uint32_t* sBm = st + 6528;
        const uint32_t* sBl = st + 8448;

        uint32_t bh[5][2], bm[5][2], bl[5][2];
#pragma unroll
        for (int nt = 0; nt < 5; nt++) {
            int bn2 = (wn * 40 + nt * 8 + lg) * 12;
            bh[nt][0] = sBh[bn2 + lt]; bh[nt][1] = sBh[bn2 + 4 + lt];
            bm[nt][0] = sBm[bn2 + lt]; bm[nt][1] = sBm[bn2 + 4 + lt];
            bl[nt][0] = sBl[bn2 + lt]; bl[nt][1] = sBl[bn2 + 4 + lt];
        }
#pragma unroll
        for (int mt = 0; mt < 4; mt++) {
            int am = (wm * 64 + mt * 16 + lg) * 12;
            int am8 = am + 8 * 12;
            uint32_t ah0 = sAh[am + lt],      ah1 = sAh[am8 + lt];
            uint32_t ah2 = sAh[am + 4 + lt],  ah3 = sAh[am8 + 4 + lt];
            uint32_t amd0 = sAm[am + lt],     amd1 = sAm[am8 + lt];
            uint32_t amd2 = sAm[am + 4 + lt], amd3 = sAm[am8 + 4 + lt];
            uint32_t alo0 = sAl[am + lt],     alo1 = sAl[am8 + lt];
            uint32_t alo2 = sAl[am + 4 + lt], alo3 = sAl[am8 + 4 + lt];
#pragma unroll
            for (int nt = 0; nt < 5; nt++) {
                mma_bf16(acc[mt][nt], ah0, ah1, ah2, ah3, bh[nt][0], bh[nt][1]);
                mma_bf16(acc[mt][nt], ah0, ah1, ah2, ah3, bm[nt][0], bm[nt][1]);
                mma_bf16(acc[mt][nt], amd0, amd1, amd2, amd3, bh[nt][0], bh[nt][1]);
                mma_bf16(acc[mt][nt], ah0, ah1, ah2, ah3, bl[nt][0], bl[nt][1]);
                mma_bf16(acc[mt][nt], alo0, alo1, alo2, alo3, bh[nt][0], bh[nt][1]);
                mma_bf16(acc[mt][nt], amd0, amd1, amd2, amd3, bm[nt][0], bm[nt][1]);
            }
        }
        __syncthreads();
    }

    // writeout
#pragma unroll
    for (int mt = 0; mt < 4; mt++) {
#pragma unroll
        for (int nt = 0; nt < 5; nt++) {
            int gn = n0 + wn * 40 + nt * 8 + 2 * lt;
            if (gn >= Ncol) continue;
            float b0 = bias[gn], b1 = bias[gn + 1];
            int gm0 = m0 + wm * 64 + mt * 16 + lg;
            if (gm0 < M) {
                float2 o = make_float2(acc[mt][nt][0] + b0, acc[mt][nt][1] + b1);
                *(float2*)(C + (size_t)gm0 * Ncol + gn) = o;
            }
            int gm1 = gm0 + 8;
            if (gm1 < M) {
                float2 o = make_float2(acc[mt][nt][2] + b0, acc[mt][nt][3] + b1);
                *(float2*)(C + (size_t)gm1 * Ncol + gn) = o;
            }
        }
    }
}

// ---------------- node aggregation: column-slice, 5 blocks/SM single wave ------
__global__ __launch_bounds__(320, 5)
void k_agg(const float* __restrict__ be_l, const float* __restrict__ We_l,
           const float* __restrict__ res_l) {
    int tid = threadIdx.x;
    int lane = tid & 31;
    int j = tid;
    bool act = (j < H);

    float wj[16];
#pragma unroll
    for (int k = 0; k < 16; k++) wj[k] = act ? We_l[k * H + j] : 0.f;
    float bj = act ? be_l[j] : 0.f;
    float rj = act ? res_l[j] : 0.f;

    float ls = 0.f, lq = 0.f;

    for (int n = blockIdx.x; n < N_NODES; n += gridDim.x) {
        float dn = g_deg[n];
        float a = act ? fmaxf(g_hp[(size_t)n * H + j] + rj, 0.f) / dn : 0.f;
        int e0 = g_rowptr[n], e1 = g_rowptr[n + 1];
        for (int e = e0; e < e1; e++) {
            int s = g_csrc[e];
            float nrm = g_enorm[e];
            float ev = (lane < FE) ? g_cef[(size_t)e * FE + lane] : 0.f;
            float ep = bj;
#pragma unroll
            for (int k = 0; k < 16; k++)
                ep = fmaf(__shfl_sync(0xffffffffu, ev, k), wj[k], ep);
            if (act) {
                float hv = g_hp[(size_t)s * H + j];
                a += nrm * fmaxf(hv + ep, 0.f);
            }
        }
        if (act) {
            g_acc[(size_t)n * H + j] = a;
            ls += a;
            lq += a * a;
        }
    }
    if (act) {
        atomicAdd(&g_sum[j], ls);
        atomicAdd(&g_sumsq[j], lq);
    }
}

// ---------------- batch norm ---------------------------------------------------

__global__ void k_zero_stats(float* __restrict__ sum, float* __restrict__ sumsq,
                             int cols) {
    int c = blockIdx.x * blockDim.x + threadIdx.x;
    if (c < cols) { sum[c] = 0.0f; sumsq[c] = 0.0f; }
}

__global__ void k_bnstat(const float* __restrict__ X, int rows, int cols,
                         float* __restrict__ sum, float* __restrict__ sumsq) {
    int r0 = blockIdx.x * 256;
    int rend = min(r0 + 256, rows);
    int t = threadIdx.x;
    float s[3] = {0, 0, 0}, q[3] = {0, 0, 0};
    for (int r = r0; r < rend; r++) {
        const float* row = X + (size_t)r * cols;
        int ci = 0;
        for (int c = t; c < cols; c += 256, ci++) {
            float v = row[c];
            s[ci] += v; q[ci] += v * v;
        }
    }
    int ci = 0;
    for (int c = t; c < cols; c += 256, ci++) {
        atomicAdd(&sum[c], s[ci]);
        atomicAdd(&sumsq[c], q[ci]);
    }
}

__global__ void k_bnfinal(int rows, int cols,
                          const float* __restrict__ sum,
                          const float* __restrict__ sumsq,
                          float* __restrict__ mean, float* __restrict__ rstd) {
    int c = blockIdx.x * blockDim.x + threadIdx.x;
    if (c < cols) {
        float m = sum[c] / (float)rows;
        float v = sumsq[c] / (float)rows - m * m;
        mean[c] = m;
        rstd[c] = rsqrtf(v + BN_EPS);
    }
}

__global__ void k_bnap(const float* __restrict__ X, float* __restrict__ Y,
                       const float* __restrict__ gamma,
                       const float* __restrict__ beta,
                       const float* __restrict__ mean,
                       const float* __restrict__ rstd,
                       int rows, int cols, int do_relu,
                       unsigned short* __restrict__ ph,
                       unsigned short* __restrict__ pm,
                       unsigned short* __restrict__ pl,
                       int pstride,
                       const int* __restrict__ gid,
                       const float* __restrict__ vfeat) {
    int idx = blockIdx.x * blockDim.x + threadIdx.x;
    if (idx < rows * cols) {
        int r = idx / cols, c = idx - r * cols;
        float v = (X[idx] - mean[c]) * rstd[c] * gamma[c] + beta[c];
        if (do_relu) v = fmaxf(v, 0.0f);
        if (Y) Y[idx] = v;
        if (ph) {
            float p = v;
            if (gid) p += vfeat[(size_t)gid[r] * cols + c];
            unsigned short h, m, lo;
            split3(p, h, m, lo);
            size_t o = (size_t)r * pstride + c;
            ph[o] = h; pm[o] = m; pl[o] = lo;
        }
    }
}

// ---------------- host orchestration -------------------------------------------

extern "C" void kernel_launch(void* const* d_in, const int* in_sizes, int n_in,
                              void* d_out, int out_size) {
    const int *node_types, *src, *dst, *gid;
    const float *edge_feats, *node_emb, *Wn, *bn_lin, *We, *be, *res_emb,
                *bn_gamma, *bn_beta, *vn_emb, *vW1, *vb1, *vg1, *vbt1,
                *vW2, *vb2, *vg2, *vbt2;

    if (in_sizes[0] == N_NODES) {
        node_types = (const int*)d_in[0];
        edge_feats = (const float*)d_in[1];
        src        = (const int*)d_in[2];
        dst        = (const int*)d_in[3];
        gid        = (const int*)d_in[4];
        node_emb = (const float*)d_in[6];
        Wn       = (const float*)d_in[7];
        bn_lin   = (const float*)d_in[8];
        We       = (const float*)d_in[9];
        be       = (const float*)d_in[10];
        res_emb  = (const float*)d_in[11];
        bn_gamma = (const float*)d_in[12];
        bn_beta  = (const float*)d_in[13];
        vn_emb   = (const float*)d_in[14];
        vW1  = (const float*)d_in[15];
        vb1  = (const float*)d_in[16];
        vg1  = (const float*)d_in[17];
        vbt1 = (const float*)d_in[18];
        vW2  = (const float*)d_in[19];
        vb2  = (const float*)d_in[20];
        vg2  = (const float*)d_in[21];
        vbt2 = (const float*)d_in[22];
    } else {
        edge_feats = (const float*)d_in[0];
        node_emb = (const float*)d_in[1];
        Wn       = (const float*)d_in[2];
        bn_lin   = (const float*)d_in[3];
        We       = (const float*)d_in[4];
        be       = (const float*)d_in[5];
        res_emb  = (const float*)d_in[6];
        bn_gamma = (const float*)d_in[7];
        bn_beta  = (const float*)d_in[8];
        vn_emb   = (const float*)d_in[9];
        vW1  = (const float*)d_in[10];
        vb1  = (const float*)d_in[11];
        vg1  = (const float*)d_in[12];
        vbt1 = (const float*)d_in[13];
        vW2  = (const float*)d_in[14];
        vb2  = (const float*)d_in[15];
        vg2  = (const float*)d_in[16];
        vbt2 = (const float*)d_in[17];
        node_types = (const int*)d_in[18];
        src        = (const int*)d_in[19];
        dst        = (const int*)d_in[20];
        gid        = (const int*)d_in[21];
    }

    const int NH = N_NODES * H;
    const int BH = BGRAPH * H;
    const int TPB = 256;

    float *g_x_p, *g_hp_p, *g_acc_p, *g_vtmp_p, *g_vfeat_p, *g_z1_p;
    cudaGetSymbolAddress((void**)&g_x_p, g_x);
    cudaGetSymbolAddress((void**)&g_hp_p, g_hp);
    cudaGetSymbolAddress((void**)&g_acc_p, g_acc);
    cudaGetSymbolAddress((void**)&g_vtmp_p, g_vtmp);
    cudaGetSymbolAddress((void**)&g_vfeat_p, g_vfeat);
    cudaGetSymbolAddress((void**)&g_z1_p, g_z1);
    float *sum_p, *sq_p, *mean_p, *rstd_p, *vsum_p, *vsq_p, *vmean_p, *vrstd_p;
    cudaGetSymbolAddress((void**)&sum_p, g_sum);
    cudaGetSymbolAddress((void**)&sq_p, g_sumsq);
    cudaGetSymbolAddress((void**)&mean_p, g_mean);
    cudaGetSymbolAddress((void**)&rstd_p, g_rstd);
    cudaGetSymbolAddress((void**)&vsum_p, g_vsumB);
    cudaGetSymbolAddress((void**)&vsq_p, g_vsqB);
    cudaGetSymbolAddress((void**)&vmean_p, g_vmeanB);
    cudaGetSymbolAddress((void**)&vrstd_p, g_vrstdB);
    unsigned short *ah_p, *am_p, *al_p, *vth_p, *vtm_p, *vtl_p,
                   *z1h_p, *z1m_p, *z1l_p, *wh_p, *wm_p, *wl_p;
    cudaGetSymbolAddress((void**)&ah_p, g_ah);
    cudaGetSymbolAddress((void**)&am_p, g_am2);
    cudaGetSymbolAddress((void**)&al_p, g_al);
    cudaGetSymbolAddress((void**)&vth_p, g_vth);
    cudaGetSymbolAddress((void**)&vtm_p, g_vtm);
    cudaGetSymbolAddress((void**)&vtl_p, g_vtl);
    cudaGetSymbolAddress((void**)&z1h_p, g_z1h);
    cudaGetSymbolAddress((void**)&z1m_p, g_z1m);
    cudaGetSymbolAddress((void**)&z1l_p, g_z1l);
    cudaGetSymbolAddress((void**)&wh_p, g_wh);
    cudaGetSymbolAddress((void**)&wm_p, g_wm);
    cudaGetSymbolAddress((void**)&wl_p, g_wl);
    const uint32_t* Ah = (const uint32_t*)ah_p;
    const uint32_t* Am = (const uint32_t*)am_p;
    const uint32_t* Al = (const uint32_t*)al_p;
    const uint32_t* VTh = (const uint32_t*)vth_p;
    const uint32_t* VTm = (const uint32_t*)vtm_p;
    const uint32_t* VTl = (const uint32_t*)vtl_p;
    const uint32_t* Z1h = (const uint32_t*)z1h_p;
    const uint32_t* Z1m = (const uint32_t*)z1m_p;
    const uint32_t* Z1l = (const uint32_t*)z1l_p;

    cudaFuncSetAttribute(k_gemm_t, cudaFuncAttributeMaxDynamicSharedMemorySize,
                         GEMM_SMEM);

    static cudaStream_t s2 = nullptr;
    static cudaEvent_t ev_fork = nullptr, ev_join = nullptr;
    if (!s2) {
        cudaStreamCreateWithFlags(&s2, cudaStreamNonBlocking);
        cudaEventCreateWithFlags(&ev_fork, cudaEventDisableTiming);
        cudaEventCreateWithFlags(&ev_join, cudaEventDisableTiming);
    }

    k_init0<<<cdiv(WTOTP, TPB), TPB>>>(Wn, vW1, vW2);
    k_count<<<cdiv(N_EDGES, TPB), TPB>>>(dst, gid);
    k_init3<<<cdiv(NH, TPB), TPB>>>(node_emb, node_types, vn_emb);
    k_gscan<<<1, 1024>>>();

    dim3 node_grid(2, AROWS / 128);

    for (int l = 0; l < LAYERS; l++) {
        const float* bnl_l = bn_lin + l * H;
        const float* We_l  = We + (size_t)l * FE * H;
        const float* be_l  = be + l * H;
        const float* res_l = res_emb + l * H;
        const float* gam_l = bn_gamma + l * H;
        const float* bet_l = bn_beta + l * H;
        const uint32_t* Wnh = (const uint32_t*)(wh_p + WNP_BASE + (size_t)l * WNP_SEG);
        const uint32_t* Wnm = (const uint32_t*)(wm_p + WNP_BASE + (size_t)l * WNP_SEG);
        const uint32_t* Wnl = (const uint32_t*)(wl_p + WNP_BASE + (size_t)l * WNP_SEG);

        bool has_vn = (l < LAYERS - 1);

        if (has_vn) {
            const float* vb1_l  = vb1 + l * H2;
            const float* vg1_l  = vg1 + l * H2;
            const float* vbt1_l = vbt1 + l * H2;
            const float* vb2_l  = vb2 + l * H;
            const float* vg2_l  = vg2 + l * H;
            const float* vbt2_l = vbt2 + l * H;
            const uint32_t* W1h = (const uint32_t*)(wh_p + VW1P_BASE + (size_t)l * VW1P_SEG);
            const uint32_t* W1m = (const uint32_t*)(wm_p + VW1P_BASE + (size_t)l * VW1P_SEG);
            const uint32_t* W1l = (const uint32_t*)(wl_p + VW1P_BASE + (size_t)l * VW1P_SEG);
            const uint32_t* W2h = (const uint32_t*)(wh_p + VW2P_BASE + (size_t)l * VW2P_SEG);
            const uint32_t* W2m = (const uint32_t*)(wm_p + VW2P_BASE + (size_t)l * VW2P_SEG);
            const uint32_t* W2l = (const uint32_t*)(wl_p + VW2P_BASE + (size_t)l * VW2P_SEG);

            cudaEventRecord(ev_fork, 0);
            cudaStreamWaitEvent(s2, ev_fork, 0);

            k_vsum<<<BGRAPH, 320, 0, s2>>>();
            dim3 g1(4, BGRAPH / 128);
            k_gemm_t<<<g1, 256, GEMM_SMEM, s2>>>(VTh, VTm, VTl, 152,
                                                 W1h, W1m, W1l, 152,
                                                 vb1_l, g_z1_p, BGRAPH, H2, 19);
            k_zero_stats<<<cdiv(H2, TPB), TPB, 0, s2>>>(vsum_p, vsq_p, H2);
            k_bnstat<<<cdiv(BGRAPH, 256), 256, 0, s2>>>(g_z1_p, BGRAPH, H2,
                                                        vsum_p, vsq_p);
            k_bnfinal<<<cdiv(H2, TPB), TPB, 0, s2>>>(BGRAPH, H2, vsum_p, vsq_p,
                                                     vmean_p, vrstd_p);
            k_bnap<<<cdiv(BGRAPH * H2, TPB), TPB, 0, s2>>>(
                g_z1_p, nullptr, vg1_l, vbt1_l, vmean_p, vrstd_p,
                BGRAPH, H2, 1, z1h_p, z1m_p, z1l_p, Z1STR, nullptr, nullptr);

            dim3 g2(2, BGRAPH / 128);
            k_gemm_t<<<g2, 256, GEMM_SMEM, s2>>>(Z1h, Z1m, Z1l, 304,
                                                 W2h, W2m, W2l, 304,
                                                 vb2_l, g_vtmp_p, BGRAPH, H, 38);
            k_zero_stats<<<cdiv(H, TPB), TPB, 0, s2>>>(vsum_p, vsq_p, H);
            k_bnstat<<<cdiv(BGRAPH, 256), 256, 0, s2>>>(g_vtmp_p, BGRAPH, H,
                                                        vsum_p, vsq_p);
            k_bnfinal<<<cdiv(H, TPB), TPB, 0, s2>>>(BGRAPH, H, vsum_p, vsq_p,
                                                    vmean_p, vrstd_p);
            k_bnap<<<cdiv(BH, TPB), TPB, 0, s2>>>(
                g_vtmp_p, g_vfeat_p, vg2_l, vbt2_l, vmean_p, vrstd_p,
                BGRAPH, H, 1, nullptr, nullptr, nullptr, 0, nullptr, nullptr);

            cudaEventRecord(ev_join, s2);
        }

        k_gemm_t<<<node_grid, 256, GEMM_SMEM>>>(Ah, Am, Al, 152,
                                                Wnh, Wnm, Wnl, 152,
                                                bnl_l, g_hp_p, N_NODES, H, 19);

        if (l == 0) {
            k_scanA<<<SCB, 1024>>>();
            k_scanB<<<1, 1>>>();
            k_scanC<<<SCB, 1024>>>();
            k_csrfill<<<cdiv(N_EDGES, TPB), TPB>>>(dst);
            k_csrdata<<<cdiv(N_EDGES * FE, TPB), TPB>>>(src, dst, edge_feats);
        }

        k_zero_stats<<<cdiv(H, TPB), TPB>>>(sum_p, sq_p, H);
        k_agg<<<740, 320>>>(be_l, We_l, res_l);
        k_bnfinal<<<cdiv(H, TPB), TPB>>>(N_NODES, H, sum_p, sq_p, mean_p, rstd_p);

        if (has_vn) {
            cudaStreamWaitEvent(0, ev_join, 0);
            k_bnap<<<cdiv(NH, TPB), TPB>>>(g_acc_p, g_x_p, gam_l, bet_l,
                                           mean_p, rstd_p, N_NODES, H, 1,
                                           ah_p, am_p, al_p, ASTR,
                                           gid, g_vfeat_p);
        } else {
            k_bnap<<<cdiv(NH, TPB), TPB>>>(g_acc_p, (float*)d_out, gam_l, bet_l,
                                           mean_p, rstd_p, N_NODES, H, 0,
                                           nullptr, nullptr, nullptr, 0,
                                           nullptr, nullptr);
        }
    }
}